// round 1
// baseline (speedup 1.0000x reference)
#include <cuda_runtime.h>
#include <cstdint>
#include <math.h>

#define HH 128
#define WW 128
#define HWs (HH*WW)
#define CC 64
#define BB 8
#define KK 9
#define CK 576

// Scratch (device globals: allocation-free kernel_launch)
__device__ float g_xnhwc[(size_t)BB * HWs * CC];     // 32 MB, NHWC
__device__ float g_offmask[(size_t)BB * HWs * 27];   // [b][pix][k][{offy,offx,mask}]
__device__ float g_act[(size_t)BB * CC * HWs];       // 32 MB, NCHW

// ---------------------------------------------------------------------------
// Kernel T: NCHW -> NHWC transpose (64 channels x 64 pixels tiles)
// ---------------------------------------------------------------------------
__global__ __launch_bounds__(256) void transpose_kernel(const float* __restrict__ x) {
    __shared__ float t[64 * 65];
    int tid = threadIdx.x;
    int blk = blockIdx.x;                 // BB * (HWs/64) = 2048 blocks
    int b  = blk >> 8;                    // HWs/64 = 256 tiles per image
    int p0 = (blk & 255) * 64;

    #pragma unroll
    for (int i = tid; i < 4096; i += 256) {
        int c  = i >> 6;
        int pl = i & 63;
        t[pl * 65 + c] = x[((size_t)b * CC + c) * HWs + p0 + pl];
    }
    __syncthreads();
    #pragma unroll
    for (int i = tid; i < 4096; i += 256) {
        int pl = i >> 6;
        int c  = i & 63;
        g_xnhwc[((size_t)b * HWs + p0 + pl) * CC + c] = t[pl * 65 + c];
    }
}

// ---------------------------------------------------------------------------
// Kernel A: 3x3 conv 64->27 producing offsets + mask (fused 2*sigmoid)
// Block: 256 threads = 16x16 output pixels. Full w_om in smem.
// ---------------------------------------------------------------------------
#define A_SMEM_FLOATS (27 * 64 * 9 + 18 * 20 + 32)
__global__ __launch_bounds__(256) void offmask_kernel(const float* __restrict__ x,
                                                      const float* __restrict__ w_om,
                                                      const float* __restrict__ b_om) {
    extern __shared__ float sm[];
    float* swt   = sm;                       // 15552
    float* stile = sm + 27 * 64 * 9;         // 18*20
    float* sb    = stile + 18 * 20;          // 27

    int tid = threadIdx.x;
    int b  = blockIdx.z;
    int by = blockIdx.y * 16;
    int bx = blockIdx.x * 16;

    for (int i = tid; i < 27 * 64 * 9; i += 256) swt[i] = w_om[i];
    if (tid < 27) sb[tid] = b_om[tid];

    float acc[27];
    #pragma unroll
    for (int oc = 0; oc < 27; ++oc) acc[oc] = 0.f;

    int ty = tid >> 4;
    int tx = tid & 15;

    for (int c = 0; c < CC; ++c) {
        __syncthreads();   // protects stile reuse + (first iter) weight load
        for (int i = tid; i < 324; i += 256) {
            int r = i / 18, col = i % 18;
            int y = by - 1 + r, xg = bx - 1 + col;
            float v = 0.f;
            if (y >= 0 && y < HH && xg >= 0 && xg < WW)
                v = x[((size_t)b * CC + c) * HWs + y * WW + xg];
            stile[r * 20 + col] = v;
        }
        __syncthreads();
        const float* wc = swt + c * 9;
        #pragma unroll
        for (int tap = 0; tap < 9; ++tap) {
            int dy = tap / 3, dx = tap % 3;
            float xv = stile[(ty + dy) * 20 + tx + dx];
            #pragma unroll
            for (int oc = 0; oc < 27; ++oc)
                acc[oc] += xv * wc[oc * 576 + tap];
        }
    }

    int pix = (by + ty) * WW + bx + tx;
    float* dst = g_offmask + ((size_t)b * HWs + pix) * 27;
    #pragma unroll
    for (int k = 0; k < KK; ++k) {
        dst[k * 3 + 0] = acc[2 * k]     + sb[2 * k];
        dst[k * 3 + 1] = acc[2 * k + 1] + sb[2 * k + 1];
        float m = acc[18 + k] + sb[18 + k];
        dst[k * 3 + 2] = 2.f / (1.f + expf(-m));
    }
}

// ---------------------------------------------------------------------------
// Kernel B: modulated deformable conv 64->64 as im2col + 32x64x576 GEMM.
// 32 pixels per block (same image row), 256 threads.
// phase1: val[32][577] built from NHWC bilinear gathers
// phase2: GEMM with 64-ck weight chunks in smem; LeakyReLU fused epilogue.
// ---------------------------------------------------------------------------
#define B_SMEM_FLOATS (32 * 577 + 64 * 65)
__global__ __launch_bounds__(256) void deform_kernel(const float* __restrict__ w_dc,
                                                     const float* __restrict__ b_dc) {
    extern __shared__ float sm[];
    float* sval = sm;                  // 32 x 577 (pad kills bank conflicts)
    float* swt  = sm + 32 * 577;       // 64 x 65

    int tid = threadIdx.x;
    int gp   = blockIdx.x * 32;
    int b    = gp / HWs;
    int pix0 = gp % HWs;
    int h    = pix0 / WW;
    int w0   = pix0 % WW;

    // ---- phase 1: gather ----
    {
        int p  = tid >> 3;       // pixel 0..31
        int cg = tid & 7;        // channel group (8 channels)
        int wp = w0 + p;
        const float* om = g_offmask + ((size_t)b * HWs + pix0 + p) * 27;

        #pragma unroll 3
        for (int k = 0; k < KK; ++k) {
            float offy = __ldg(om + k * 3 + 0);
            float offx = __ldg(om + k * 3 + 1);
            float msk  = __ldg(om + k * 3 + 2);
            float py = (float)(h - 1 + k / 3) + offy;
            float px = (float)(wp - 1 + k % 3) + offx;
            float y0f = floorf(py), x0f = floorf(px);
            float ly = py - y0f, lx = px - x0f;
            int y0 = (int)y0f, x0 = (int)x0f;

            float v[8];
            #pragma unroll
            for (int j = 0; j < 8; ++j) v[j] = 0.f;

            float wts[4] = {(1.f - ly) * (1.f - lx), (1.f - ly) * lx,
                            ly * (1.f - lx),          ly * lx};
            int ys[4] = {y0, y0, y0 + 1, y0 + 1};
            int xs[4] = {x0, x0 + 1, x0, x0 + 1};
            #pragma unroll
            for (int s = 0; s < 4; ++s) {
                int yy = ys[s], xx = xs[s];
                if (yy >= 0 && yy < HH && xx >= 0 && xx < WW) {
                    const float4* src = (const float4*)(g_xnhwc +
                        (((size_t)b * HWs + (size_t)yy * WW + xx) * CC + cg * 8));
                    float4 a0 = __ldg(src);
                    float4 a1 = __ldg(src + 1);
                    float wgt = wts[s];
                    v[0] += wgt * a0.x; v[1] += wgt * a0.y;
                    v[2] += wgt * a0.z; v[3] += wgt * a0.w;
                    v[4] += wgt * a1.x; v[5] += wgt * a1.y;
                    v[6] += wgt * a1.z; v[7] += wgt * a1.w;
                }
            }
            int base = p * 577 + (cg * 8) * 9 + k;   // ck = c*9 + k
            #pragma unroll
            for (int j = 0; j < 8; ++j)
                sval[base + j * 9] = v[j] * msk;
        }
    }
    __syncthreads();

    // ---- phase 2: GEMM out[32p][64o] = val[32p][576] * W^T ----
    int pp = (tid & 15) * 2;    // 2 pixels per thread
    int og = tid >> 4;          // 4 output channels per thread
    float acc0[4] = {0.f, 0.f, 0.f, 0.f};
    float acc1[4] = {0.f, 0.f, 0.f, 0.f};

    for (int ck0 = 0; ck0 < CK; ck0 += 64) {
        if (ck0) __syncthreads();
        for (int i = tid; i < 4096; i += 256) {
            int o = i >> 6, ckl = i & 63;
            swt[ckl * 65 + o] = __ldg(w_dc + (size_t)o * CK + ck0 + ckl);
        }
        __syncthreads();
        const float* v0p = sval + pp * 577 + ck0;
        const float* v1p = v0p + 577;
        #pragma unroll 8
        for (int ckl = 0; ckl < 64; ++ckl) {
            float a0 = v0p[ckl];
            float a1 = v1p[ckl];
            const float* wr = &swt[ckl * 65 + og * 4];
            #pragma unroll
            for (int j = 0; j < 4; ++j) {
                float wv = wr[j];
                acc0[j] += a0 * wv;
                acc1[j] += a1 * wv;
            }
        }
    }

    #pragma unroll
    for (int j = 0; j < 4; ++j) {
        int o = og * 4 + j;
        float bb = __ldg(b_dc + o);
        float u0 = acc0[j] + bb, u1 = acc1[j] + bb;
        u0 = u0 > 0.f ? u0 : 0.2f * u0;
        u1 = u1 > 0.f ? u1 : 0.2f * u1;
        size_t base = ((size_t)b * CC + o) * HWs + pix0;
        g_act[base + pp]     = u0;
        g_act[base + pp + 1] = u1;
    }
}

// ---------------------------------------------------------------------------
// Kernel C: 3x3 conv 64->64 on act (NCHW) + bias + residual x.
// Same GEMM skeleton; im2col comes from a 64ch x 3row x 40col smem tile.
// ---------------------------------------------------------------------------
#define C_SMEM_FLOATS (64 * 3 * 40 + 64 * 65)
__global__ __launch_bounds__(256) void conv2_kernel(const float* __restrict__ x,
                                                    const float* __restrict__ w_c,
                                                    const float* __restrict__ b_c,
                                                    float* __restrict__ out) {
    extern __shared__ float sm[];
    float* atile = sm;                 // [c][3][40], 34 cols used
    float* swt   = sm + 64 * 3 * 40;   // 64 x 65

    int tid = threadIdx.x;
    int gp   = blockIdx.x * 32;
    int b    = gp / HWs;
    int pix0 = gp % HWs;
    int h    = pix0 / WW;
    int w0   = pix0 % WW;

    for (int i = tid; i < 64 * 3 * 34; i += 256) {
        int c = i / 102;
        int rem = i % 102;
        int r = rem / 34, col = rem % 34;
        int y = h - 1 + r, xg = w0 - 1 + col;
        float v = 0.f;
        if (y >= 0 && y < HH && xg >= 0 && xg < WW)
            v = g_act[((size_t)b * CC + c) * HWs + y * WW + xg];
        atile[c * 120 + r * 40 + col] = v;
    }
    __syncthreads();

    int pp = (tid & 15) * 2;
    int og = tid >> 4;
    float acc0[4] = {0.f, 0.f, 0.f, 0.f};
    float acc1[4] = {0.f, 0.f, 0.f, 0.f};

    int c = 0, tap = 0, abase = 0;     // abase = c*120 + dy*40 + dx
    for (int ck0 = 0; ck0 < CK; ck0 += 64) {
        if (ck0) __syncthreads();
        for (int i = tid; i < 4096; i += 256) {
            int o = i >> 6, ckl = i & 63;
            swt[ckl * 65 + o] = __ldg(w_c + (size_t)o * CK + ck0 + ckl);
        }
        __syncthreads();
        for (int ckl = 0; ckl < 64; ++ckl) {
            float a0 = atile[abase + pp];
            float a1 = atile[abase + pp + 1];
            const float* wr = &swt[ckl * 65 + og * 4];
            #pragma unroll
            for (int j = 0; j < 4; ++j) {
                float wv = wr[j];
                acc0[j] += a0 * wv;
                acc1[j] += a1 * wv;
            }
            // advance (c, tap) and abase
            ++tap;
            ++abase;
            if (tap == 3 || tap == 6) abase += 37;   // next dy row
            if (tap == 9) { tap = 0; ++c; abase = c * 120; }
        }
    }

    #pragma unroll
    for (int j = 0; j < 4; ++j) {
        int o = og * 4 + j;
        size_t base = ((size_t)b * CC + o) * HWs + pix0;
        float r0 = acc0[j] + __ldg(b_c + o) + __ldg(x + base + pp);
        float r1 = acc1[j] + __ldg(b_c + o) + __ldg(x + base + pp + 1);
        out[base + pp]     = r0;
        out[base + pp + 1] = r1;
    }
}

// ---------------------------------------------------------------------------
extern "C" void kernel_launch(void* const* d_in, const int* in_sizes, int n_in,
                              void* d_out, int out_size) {
    const float* x    = (const float*)d_in[0];
    const float* w_om = (const float*)d_in[1];
    const float* b_om = (const float*)d_in[2];
    const float* w_dc = (const float*)d_in[3];
    const float* b_dc = (const float*)d_in[4];
    const float* w_c  = (const float*)d_in[5];
    const float* b_c  = (const float*)d_in[6];
    float* out = (float*)d_out;

    cudaFuncSetAttribute(offmask_kernel, cudaFuncAttributeMaxDynamicSharedMemorySize,
                         A_SMEM_FLOATS * (int)sizeof(float));
    cudaFuncSetAttribute(deform_kernel, cudaFuncAttributeMaxDynamicSharedMemorySize,
                         B_SMEM_FLOATS * (int)sizeof(float));
    cudaFuncSetAttribute(conv2_kernel, cudaFuncAttributeMaxDynamicSharedMemorySize,
                         C_SMEM_FLOATS * (int)sizeof(float));

    transpose_kernel<<<BB * (HWs / 64), 256>>>(x);

    dim3 gridA(WW / 16, HH / 16, BB);
    offmask_kernel<<<gridA, 256, A_SMEM_FLOATS * sizeof(float)>>>(x, w_om, b_om);

    deform_kernel<<<BB * HWs / 32, 256, B_SMEM_FLOATS * sizeof(float)>>>(w_dc, b_dc);

    conv2_kernel<<<BB * HWs / 32, 256, C_SMEM_FLOATS * sizeof(float)>>>(x, w_c, b_c, out);
}

// round 2
// speedup vs baseline: 1.6473x; 1.6473x over previous
#include <cuda_runtime.h>
#include <cstdint>
#include <math.h>

#define HH 128
#define WW 128
#define HWs (HH*WW)
#define CC 64
#define BB 8
#define KK 9
#define CK 576

// Scratch (device globals: allocation-free kernel_launch)
__device__ float g_xnhwc[(size_t)BB * HWs * CC];     // NHWC copy of x
__device__ float g_offmask[(size_t)BB * HWs * 27];   // [b][pix][k][{offy,offx,mask}]
__device__ float g_act[(size_t)BB * CC * HWs];       // NCHW leaky output
__device__ float g_wdcT[CK * CC];                    // w_dc transposed [ck][oc]
__device__ float g_wcT[CK * CC];                     // w_c  transposed [ck][oc]

// ---------------------------------------------------------------------------
// Kernel W: transpose both GEMM weight matrices [64][576] -> [576][64]
// ---------------------------------------------------------------------------
__global__ __launch_bounds__(256) void wtrans_kernel(const float* __restrict__ w_dc,
                                                     const float* __restrict__ w_c) {
    int i = blockIdx.x * 256 + threadIdx.x;
    if (i < CK * CC) {
        int o = i / CK, ck = i % CK;
        g_wdcT[ck * CC + o] = w_dc[i];
    } else if (i < 2 * CK * CC) {
        int j = i - CK * CC;
        int o = j / CK, ck = j % CK;
        g_wcT[ck * CC + o] = w_c[j];
    }
}

// ---------------------------------------------------------------------------
// Kernel T: NCHW -> NHWC transpose
// ---------------------------------------------------------------------------
__global__ __launch_bounds__(256) void transpose_kernel(const float* __restrict__ x) {
    __shared__ float t[64 * 65];
    int tid = threadIdx.x;
    int blk = blockIdx.x;
    int b  = blk >> 8;
    int p0 = (blk & 255) * 64;

    #pragma unroll
    for (int i = tid; i < 4096; i += 256) {
        int c  = i >> 6;
        int pl = i & 63;
        t[pl * 65 + c] = x[((size_t)b * CC + c) * HWs + p0 + pl];
    }
    __syncthreads();
    #pragma unroll
    for (int i = tid; i < 4096; i += 256) {
        int pl = i >> 6;
        int c  = i & 63;
        g_xnhwc[((size_t)b * HWs + p0 + pl) * CC + c] = t[pl * 65 + c];
    }
}

// ---------------------------------------------------------------------------
// Kernel A: 3x3 conv 64->27 (offsets + 2*sigmoid mask).
// 16x16 px tile, 256 threads, channel-chunked by 16.
// Weights in smem as [c][tap][28] -> 7 float4 broadcast loads per tap.
// ---------------------------------------------------------------------------
#define A_SMEM_FLOATS (16*18*20 + 16*9*28 + 32)
__global__ __launch_bounds__(256) void offmask_kernel(const float* __restrict__ x,
                                                      const float* __restrict__ w_om,
                                                      const float* __restrict__ b_om) {
    extern __shared__ float sm[];
    float* stile = sm;                 // 16 ch x 18 rows x 20 cols
    float* sw    = sm + 16 * 18 * 20;  // 144 x 28
    float* sb    = sw + 16 * 9 * 28;   // 27

    int tid = threadIdx.x;
    int b  = blockIdx.z;
    int by = blockIdx.y * 16;
    int bx = blockIdx.x * 16;
    if (tid < 27) sb[tid] = b_om[tid];

    float acc[27];
    #pragma unroll
    for (int oc = 0; oc < 27; ++oc) acc[oc] = 0.f;

    int ty = tid >> 4;
    int tx = tid & 15;

    for (int c0 = 0; c0 < CC; c0 += 16) {
        __syncthreads();
        // input tile: 16 ch x 18x18 (stored stride 20)
        for (int i = tid; i < 16 * 324; i += 256) {
            int c = i / 324;
            int rem = i % 324;
            int r = rem / 18, col = rem % 18;
            int y = by - 1 + r, xg = bx - 1 + col;
            float v = 0.f;
            if (y >= 0 && y < HH && xg >= 0 && xg < WW)
                v = x[((size_t)b * CC + c0 + c) * HWs + y * WW + xg];
            stile[c * 360 + r * 20 + col] = v;
        }
        // weights: [ct=c*9+tap][oc], padded to 28
        for (int i = tid; i < 16 * 9 * 27; i += 256) {
            int ct = i / 27, oc = i % 27;
            sw[ct * 28 + oc] = w_om[oc * 576 + c0 * 9 + ct];
        }
        __syncthreads();

        #pragma unroll 2
        for (int c = 0; c < 16; ++c) {
            #pragma unroll
            for (int tap = 0; tap < 9; ++tap) {
                float xv = stile[c * 360 + (ty + tap / 3) * 20 + tx + tap % 3];
                const float4* wv = (const float4*)&sw[(c * 9 + tap) * 28];
                #pragma unroll
                for (int j = 0; j < 7; ++j) {
                    float4 w4 = wv[j];
                    acc[4 * j + 0] += xv * w4.x;
                    if (4 * j + 1 < 27) acc[4 * j + 1] += xv * w4.y;
                    if (4 * j + 2 < 27) acc[4 * j + 2] += xv * w4.z;
                    if (4 * j + 3 < 27) acc[4 * j + 3] += xv * w4.w;
                }
            }
        }
    }

    int pix = (by + ty) * WW + bx + tx;
    float* dst = g_offmask + ((size_t)b * HWs + pix) * 27;
    #pragma unroll
    for (int k = 0; k < KK; ++k) {
        dst[k * 3 + 0] = acc[2 * k]     + sb[2 * k];
        dst[k * 3 + 1] = acc[2 * k + 1] + sb[2 * k + 1];
        float m = acc[18 + k] + sb[18 + k];
        dst[k * 3 + 2] = 2.f / (1.f + expf(-m));
    }
}

// ---------------------------------------------------------------------------
// Kernel B: modulated deformable conv 64->64.
// Block = one image row (128 px), 256 threads.
// Tap-chunked: per tap gather sval[64ch][128px+4] + weight chunk [64ck][64oc],
// GEMM thread tile 4px x 8oc (32 acc). LeakyReLU fused.
// ---------------------------------------------------------------------------
#define B_SMEM_FLOATS (64*132 + 64*64)
__global__ __launch_bounds__(256, 2) void deform_kernel(const float* __restrict__ b_dc) {
    extern __shared__ float sm[];
    float* sval = sm;              // [64][132]
    float* swk  = sm + 64 * 132;   // [64][64]

    int tid = threadIdx.x;
    int blk = blockIdx.x;
    int b = blk >> 7;
    int h = blk & 127;

    int p    = tid & 127;          // pixel (gather role)
    int half = tid >> 7;           // channel half (gather role)
    const float* om = g_offmask + ((size_t)b * HWs + h * WW + p) * 27;
    const float* xb = g_xnhwc + (size_t)b * HWs * CC;

    int pxg = tid & 31;            // GEMM: 4-px group
    int ocg = tid >> 5;            // GEMM: 8-oc group

    float4 acc[8];
    #pragma unroll
    for (int j = 0; j < 8; ++j) acc[j] = make_float4(0.f, 0.f, 0.f, 0.f);

    #pragma unroll 1
    for (int tap = 0; tap < KK; ++tap) {
        if (tap) __syncthreads();
        // weight chunk for this tap: swk[c][o]
        #pragma unroll
        for (int i = tid; i < 4096; i += 256) {
            int c = i >> 6, o = i & 63;
            swk[i] = g_wdcT[(c * 9 + tap) * CC + o];
        }
        // gather: this thread fills channels [half*32, half*32+32) of pixel p
        {
            float offy = __ldg(om + tap * 3 + 0);
            float offx = __ldg(om + tap * 3 + 1);
            float msk  = __ldg(om + tap * 3 + 2);
            float py = (float)(h - 1 + tap / 3) + offy;
            float px = (float)(p - 1 + tap % 3) + offx;
            float y0f = floorf(py), x0f = floorf(px);
            float ly = py - y0f, lx = px - x0f;
            int y0 = (int)y0f, x0 = (int)x0f;

            float wq[4] = {(1.f - ly) * (1.f - lx) * msk,
                           (1.f - ly) * lx * msk,
                           ly * (1.f - lx) * msk,
                           ly * lx * msk};
            int ys[4] = {y0, y0, y0 + 1, y0 + 1};
            int xs[4] = {x0, x0 + 1, x0, x0 + 1};
            bool vd[4];
            size_t addr[4];
            #pragma unroll
            for (int s = 0; s < 4; ++s) {
                vd[s] = (ys[s] >= 0) & (ys[s] < HH) & (xs[s] >= 0) & (xs[s] < WW);
                addr[s] = ((size_t)(ys[s] * WW + xs[s])) * CC;
            }

            #pragma unroll
            for (int q = 0; q < 4; ++q) {
                int cb = half * 32 + q * 8;
                float4 u0 = make_float4(0.f, 0.f, 0.f, 0.f);
                float4 u1 = make_float4(0.f, 0.f, 0.f, 0.f);
                #pragma unroll
                for (int s = 0; s < 4; ++s) {
                    if (vd[s]) {
                        const float4* sp = (const float4*)(xb + addr[s] + cb);
                        float4 a0 = __ldg(sp);
                        float4 a1 = __ldg(sp + 1);
                        float wgt = wq[s];
                        u0.x += wgt * a0.x; u0.y += wgt * a0.y;
                        u0.z += wgt * a0.z; u0.w += wgt * a0.w;
                        u1.x += wgt * a1.x; u1.y += wgt * a1.y;
                        u1.z += wgt * a1.z; u1.w += wgt * a1.w;
                    }
                }
                float* d = sval + cb * 132 + p;
                d[0 * 132] = u0.x; d[1 * 132] = u0.y;
                d[2 * 132] = u0.z; d[3 * 132] = u0.w;
                d[4 * 132] = u1.x; d[5 * 132] = u1.y;
                d[6 * 132] = u1.z; d[7 * 132] = u1.w;
            }
        }
        __syncthreads();

        // GEMM: acc[oc][4px] += sval * swk for 64 channels of this tap
        const float* sv = sval + pxg * 4;
        const float* wr = swk + ocg * 8;
        #pragma unroll 4
        for (int c = 0; c < 64; ++c) {
            float4 a  = *(const float4*)(sv + c * 132);
            float4 w0 = *(const float4*)(wr + c * 64);
            float4 w1 = *(const float4*)(wr + c * 64 + 4);
            acc[0].x += a.x * w0.x; acc[0].y += a.y * w0.x; acc[0].z += a.z * w0.x; acc[0].w += a.w * w0.x;
            acc[1].x += a.x * w0.y; acc[1].y += a.y * w0.y; acc[1].z += a.z * w0.y; acc[1].w += a.w * w0.y;
            acc[2].x += a.x * w0.z; acc[2].y += a.y * w0.z; acc[2].z += a.z * w0.z; acc[2].w += a.w * w0.z;
            acc[3].x += a.x * w0.w; acc[3].y += a.y * w0.w; acc[3].z += a.z * w0.w; acc[3].w += a.w * w0.w;
            acc[4].x += a.x * w1.x; acc[4].y += a.y * w1.x; acc[4].z += a.z * w1.x; acc[4].w += a.w * w1.x;
            acc[5].x += a.x * w1.y; acc[5].y += a.y * w1.y; acc[5].z += a.z * w1.y; acc[5].w += a.w * w1.y;
            acc[6].x += a.x * w1.z; acc[6].y += a.y * w1.z; acc[6].z += a.z * w1.z; acc[6].w += a.w * w1.z;
            acc[7].x += a.x * w1.w; acc[7].y += a.y * w1.w; acc[7].z += a.z * w1.w; acc[7].w += a.w * w1.w;
        }
    }

    // epilogue: bias + LeakyReLU -> g_act (NCHW)
    #pragma unroll
    for (int j = 0; j < 8; ++j) {
        int o = ocg * 8 + j;
        float bb = __ldg(b_dc + o);
        float4 v = acc[j];
        v.x += bb; v.y += bb; v.z += bb; v.w += bb;
        v.x = v.x > 0.f ? v.x : 0.2f * v.x;
        v.y = v.y > 0.f ? v.y : 0.2f * v.y;
        v.z = v.z > 0.f ? v.z : 0.2f * v.z;
        v.w = v.w > 0.f ? v.w : 0.2f * v.w;
        *(float4*)(g_act + ((size_t)b * CC + o) * HWs + h * WW + pxg * 4) = v;
    }
}

// ---------------------------------------------------------------------------
// Kernel C: 3x3 conv 64->64 on act + bias + residual.
// Block = one image row (128 px). Channel-chunked by 16.
// Act tile [16ch][3rows][132], weights [144ck][64oc]. 4px x 8oc per thread.
// ---------------------------------------------------------------------------
#define C_SMEM_FLOATS (16*3*132 + 144*64)
__global__ __launch_bounds__(256, 2) void conv2_kernel(const float* __restrict__ x,
                                                       const float* __restrict__ b_c,
                                                       float* __restrict__ out) {
    extern __shared__ float sm[];
    float* atile = sm;             // [16][3][132], col j = x+1 (x in -1..128), j<=129 used
    float* swc   = sm + 16 * 396;  // [144][64]

    int tid = threadIdx.x;
    int blk = blockIdx.x;
    int b = blk >> 7;
    int h = blk & 127;

    int pxg = tid & 31;
    int ocg = tid >> 5;

    float4 acc[8];
    #pragma unroll
    for (int j = 0; j < 8; ++j) acc[j] = make_float4(0.f, 0.f, 0.f, 0.f);

    for (int cg = 0; cg < 4; ++cg) {
        if (cg) __syncthreads();
        // act tile
        for (int i = tid; i < 16 * 396; i += 256) {
            int c = i / 396;
            int rem = i % 396;
            int r = rem / 132, j = rem % 132;
            int y = h - 1 + r;
            int xg = j - 1;
            float v = 0.f;
            if (y >= 0 && y < HH && xg >= 0 && xg < WW)
                v = g_act[((size_t)b * CC + cg * 16 + c) * HWs + y * WW + xg];
            atile[i] = v;
        }
        // weight chunk: 144 x 64 (ck-major, coalesced)
        for (int i = tid; i < 144 * 64; i += 256)
            swc[i] = g_wcT[cg * 144 * 64 + i];
        __syncthreads();

        const float* wr = swc + ocg * 8;
        #pragma unroll 1
        for (int c = 0; c < 16; ++c) {
            #pragma unroll
            for (int dy = 0; dy < 3; ++dy) {
                const float* ar = atile + c * 396 + dy * 132 + pxg * 4;
                float4 alo = *(const float4*)ar;
                float2 ahi = *(const float2*)(ar + 4);
                float av[6] = {alo.x, alo.y, alo.z, alo.w, ahi.x, ahi.y};
                #pragma unroll
                for (int dx = 0; dx < 3; ++dx) {
                    int ck = c * 9 + dy * 3 + dx;
                    float4 w0 = *(const float4*)(wr + ck * 64);
                    float4 w1 = *(const float4*)(wr + ck * 64 + 4);
                    float a0 = av[dx], a1 = av[dx + 1], a2 = av[dx + 2], a3 = av[dx + 3];
                    acc[0].x += a0 * w0.x; acc[0].y += a1 * w0.x; acc[0].z += a2 * w0.x; acc[0].w += a3 * w0.x;
                    acc[1].x += a0 * w0.y; acc[1].y += a1 * w0.y; acc[1].z += a2 * w0.y; acc[1].w += a3 * w0.y;
                    acc[2].x += a0 * w0.z; acc[2].y += a1 * w0.z; acc[2].z += a2 * w0.z; acc[2].w += a3 * w0.z;
                    acc[3].x += a0 * w0.w; acc[3].y += a1 * w0.w; acc[3].z += a2 * w0.w; acc[3].w += a3 * w0.w;
                    acc[4].x += a0 * w1.x; acc[4].y += a1 * w1.x; acc[4].z += a2 * w1.x; acc[4].w += a3 * w1.x;
                    acc[5].x += a0 * w1.y; acc[5].y += a1 * w1.y; acc[5].z += a2 * w1.y; acc[5].w += a3 * w1.y;
                    acc[6].x += a0 * w1.z; acc[6].y += a1 * w1.z; acc[6].z += a2 * w1.z; acc[6].w += a3 * w1.z;
                    acc[7].x += a0 * w1.w; acc[7].y += a1 * w1.w; acc[7].z += a2 * w1.w; acc[7].w += a3 * w1.w;
                }
            }
        }
    }

    // epilogue: bias + residual
    #pragma unroll
    for (int j = 0; j < 8; ++j) {
        int o = ocg * 8 + j;
        size_t base = ((size_t)b * CC + o) * HWs + h * WW + pxg * 4;
        float bb = __ldg(b_c + o);
        float4 r = *(const float4*)(x + base);
        float4 v = acc[j];
        v.x += bb + r.x; v.y += bb + r.y; v.z += bb + r.z; v.w += bb + r.w;
        *(float4*)(out + base) = v;
    }
}

// ---------------------------------------------------------------------------
extern "C" void kernel_launch(void* const* d_in, const int* in_sizes, int n_in,
                              void* d_out, int out_size) {
    const float* x    = (const float*)d_in[0];
    const float* w_om = (const float*)d_in[1];
    const float* b_om = (const float*)d_in[2];
    const float* w_dc = (const float*)d_in[3];
    const float* b_dc = (const float*)d_in[4];
    const float* w_c  = (const float*)d_in[5];
    const float* b_c  = (const float*)d_in[6];
    float* out = (float*)d_out;

    cudaFuncSetAttribute(offmask_kernel, cudaFuncAttributeMaxDynamicSharedMemorySize,
                         A_SMEM_FLOATS * (int)sizeof(float));
    cudaFuncSetAttribute(deform_kernel, cudaFuncAttributeMaxDynamicSharedMemorySize,
                         B_SMEM_FLOATS * (int)sizeof(float));
    cudaFuncSetAttribute(conv2_kernel, cudaFuncAttributeMaxDynamicSharedMemorySize,
                         C_SMEM_FLOATS * (int)sizeof(float));

    wtrans_kernel<<<(2 * CK * CC + 255) / 256, 256>>>(w_dc, w_c);
    transpose_kernel<<<BB * (HWs / 64), 256>>>(x);

    dim3 gridA(WW / 16, HH / 16, BB);
    offmask_kernel<<<gridA, 256, A_SMEM_FLOATS * sizeof(float)>>>(x, w_om, b_om);

    deform_kernel<<<BB * HH, 256, B_SMEM_FLOATS * sizeof(float)>>>(b_dc);

    conv2_kernel<<<BB * HH, 256, C_SMEM_FLOATS * sizeof(float)>>>(x, b_c, out);
}

// round 3
// speedup vs baseline: 2.0684x; 1.2556x over previous
#include <cuda_runtime.h>
#include <cstdint>
#include <math.h>

#define HH 128
#define WW 128
#define HWs (HH*WW)
#define CC 64
#define BB 8
#define KK 9
#define CK 576

// Scratch (device globals: allocation-free kernel_launch)
__device__ float g_xnhwc[(size_t)BB * HWs * CC];     // NHWC copy of x
__device__ float g_offmask[(size_t)BB * HWs * 27];   // [b][pix][k][{offy,offx,mask}]
__device__ float g_act[(size_t)BB * CC * HWs];       // NCHW leaky output

// ---------------------------------------------------------------------------
// helpers: tf32 convert + m16n8k8 tf32 mma
// ---------------------------------------------------------------------------
__device__ __forceinline__ float to_tf32(float f) {
    uint32_t u;
    asm("cvt.rna.tf32.f32 %0, %1;" : "=r"(u) : "f"(f));
    return __uint_as_float(u);
}

__device__ __forceinline__ void mma8(float4& d, const uint32_t* a, const uint32_t* bf) {
    asm volatile(
        "mma.sync.aligned.m16n8k8.row.col.f32.tf32.tf32.f32 "
        "{%0,%1,%2,%3},{%4,%5,%6,%7},{%8,%9},{%0,%1,%2,%3};\n"
        : "+f"(d.x), "+f"(d.y), "+f"(d.z), "+f"(d.w)
        : "r"(a[0]), "r"(a[1]), "r"(a[2]), "r"(a[3]), "r"(bf[0]), "r"(bf[1]));
}

// ---------------------------------------------------------------------------
// Kernel T: NCHW -> NHWC transpose
// ---------------------------------------------------------------------------
__global__ __launch_bounds__(256) void transpose_kernel(const float* __restrict__ x) {
    __shared__ float t[64 * 65];
    int tid = threadIdx.x;
    int blk = blockIdx.x;
    int b  = blk >> 8;
    int p0 = (blk & 255) * 64;

    #pragma unroll
    for (int i = tid; i < 4096; i += 256) {
        int c  = i >> 6;
        int pl = i & 63;
        t[pl * 65 + c] = x[((size_t)b * CC + c) * HWs + p0 + pl];
    }
    __syncthreads();
    #pragma unroll
    for (int i = tid; i < 4096; i += 256) {
        int pl = i >> 6;
        int c  = i & 63;
        g_xnhwc[((size_t)b * HWs + p0 + pl) * CC + c] = t[pl * 65 + c];
    }
}

// ---------------------------------------------------------------------------
// Kernel A: 3x3 conv 64->27 (offsets + 2*sigmoid mask). fp32 (precision).
// ---------------------------------------------------------------------------
#define A_SMEM_FLOATS (16*18*20 + 16*9*28 + 32)
__global__ __launch_bounds__(256) void offmask_kernel(const float* __restrict__ x,
                                                      const float* __restrict__ w_om,
                                                      const float* __restrict__ b_om) {
    extern __shared__ float sm[];
    float* stile = sm;                 // 16 ch x 18 rows x 20 cols
    float* sw    = sm + 16 * 18 * 20;  // 144 x 28
    float* sb    = sw + 16 * 9 * 28;   // 27

    int tid = threadIdx.x;
    int b  = blockIdx.z;
    int by = blockIdx.y * 16;
    int bx = blockIdx.x * 16;
    if (tid < 27) sb[tid] = b_om[tid];

    float acc[27];
    #pragma unroll
    for (int oc = 0; oc < 27; ++oc) acc[oc] = 0.f;

    int ty = tid >> 4;
    int tx = tid & 15;

    for (int c0 = 0; c0 < CC; c0 += 16) {
        __syncthreads();
        for (int i = tid; i < 16 * 324; i += 256) {
            int c = i / 324;
            int rem = i % 324;
            int r = rem / 18, col = rem % 18;
            int y = by - 1 + r, xg = bx - 1 + col;
            float v = 0.f;
            if (y >= 0 && y < HH && xg >= 0 && xg < WW)
                v = x[((size_t)b * CC + c0 + c) * HWs + y * WW + xg];
            stile[c * 360 + r * 20 + col] = v;
        }
        for (int i = tid; i < 16 * 9 * 27; i += 256) {
            int ct = i / 27, oc = i % 27;
            sw[ct * 28 + oc] = w_om[oc * 576 + c0 * 9 + ct];
        }
        __syncthreads();

        #pragma unroll 2
        for (int c = 0; c < 16; ++c) {
            #pragma unroll
            for (int tap = 0; tap < 9; ++tap) {
                float xv = stile[c * 360 + (ty + tap / 3) * 20 + tx + tap % 3];
                const float4* wv = (const float4*)&sw[(c * 9 + tap) * 28];
                #pragma unroll
                for (int j = 0; j < 7; ++j) {
                    float4 w4 = wv[j];
                    acc[4 * j + 0] += xv * w4.x;
                    if (4 * j + 1 < 27) acc[4 * j + 1] += xv * w4.y;
                    if (4 * j + 2 < 27) acc[4 * j + 2] += xv * w4.z;
                    if (4 * j + 3 < 27) acc[4 * j + 3] += xv * w4.w;
                }
            }
        }
    }

    int pix = (by + ty) * WW + bx + tx;
    float* dst = g_offmask + ((size_t)b * HWs + pix) * 27;
    #pragma unroll
    for (int k = 0; k < KK; ++k) {
        dst[k * 3 + 0] = acc[2 * k]     + sb[2 * k];
        dst[k * 3 + 1] = acc[2 * k + 1] + sb[2 * k + 1];
        float m = acc[18 + k] + sb[18 + k];
        dst[k * 3 + 2] = 2.f / (1.f + expf(-m));
    }
}

// ---------------------------------------------------------------------------
// Kernel B: modulated deformable conv 64->64, tf32 tensor-core GEMM.
// Block = one image row (128 px), 256 threads (8 warps).
// Per tap: gather -> sval[64ck][136px] (tf32), weights -> swk[64oc][68] (tf32),
// then 8 x m16n8k8 k-steps. Warp tile 32px x 32oc. LeakyReLU fused.
// ---------------------------------------------------------------------------
#define B_SMEM_FLOATS (64*136 + 64*68)
__global__ __launch_bounds__(256, 2) void deform_kernel(const float* __restrict__ w_dc,
                                                        const float* __restrict__ b_dc) {
    extern __shared__ float sm[];
    float* sval = sm;              // [64][136]
    float* swk  = sm + 64 * 136;   // [64][68]

    int tid = threadIdx.x;
    int b = blockIdx.x >> 7;
    int h = blockIdx.x & 127;

    int lane = tid & 31, wid = tid >> 5;
    int warp_m = wid & 3;          // 4 x 32 px
    int warp_n = wid >> 2;         // 2 x 32 oc
    int lq = lane >> 2, lr = lane & 3;

    // gather role
    int p     = tid & 127;
    int half_ = tid >> 7;
    const float* om = g_offmask + ((size_t)b * HWs + h * WW + p) * 27;
    const float* xb = g_xnhwc + (size_t)b * HWs * CC;

    float4 acc[2][4];
    #pragma unroll
    for (int mt = 0; mt < 2; ++mt)
        #pragma unroll
        for (int nt = 0; nt < 4; ++nt) acc[mt][nt] = make_float4(0.f, 0.f, 0.f, 0.f);

    #pragma unroll 1
    for (int tap = 0; tap < KK; ++tap) {
        __syncthreads();
        // weights transposed: swk[o][c] = w_dc[o][c*9+tap]
        #pragma unroll
        for (int i = tid; i < 4096; i += 256) {
            int o = i >> 6, c = i & 63;
            swk[o * 68 + c] = to_tf32(__ldg(w_dc + (size_t)o * CK + c * 9 + tap));
        }
        // gather: channels [half_*32, +32) of pixel p for this tap
        {
            float offy = __ldg(om + tap * 3 + 0);
            float offx = __ldg(om + tap * 3 + 1);
            float msk  = __ldg(om + tap * 3 + 2);
            float py = (float)(h - 1 + tap / 3) + offy;
            float px = (float)(p - 1 + tap % 3) + offx;
            float y0f = floorf(py), x0f = floorf(px);
            float ly = py - y0f, lx = px - x0f;
            int y0 = (int)y0f, x0 = (int)x0f;

            float wq[4] = {(1.f - ly) * (1.f - lx) * msk,
                           (1.f - ly) * lx * msk,
                           ly * (1.f - lx) * msk,
                           ly * lx * msk};
            int ys[4] = {y0, y0, y0 + 1, y0 + 1};
            int xs[4] = {x0, x0 + 1, x0, x0 + 1};
            bool vd[4];
            size_t addr[4];
            #pragma unroll
            for (int s = 0; s < 4; ++s) {
                vd[s] = (ys[s] >= 0) & (ys[s] < HH) & (xs[s] >= 0) & (xs[s] < WW);
                addr[s] = ((size_t)(ys[s] * WW + xs[s])) * CC;
            }

            #pragma unroll
            for (int q = 0; q < 4; ++q) {
                int cb = half_ * 32 + q * 8;
                float4 u0 = make_float4(0.f, 0.f, 0.f, 0.f);
                float4 u1 = make_float4(0.f, 0.f, 0.f, 0.f);
                #pragma unroll
                for (int s = 0; s < 4; ++s) {
                    if (vd[s]) {
                        const float4* sp = (const float4*)(xb + addr[s] + cb);
                        float4 a0 = __ldg(sp);
                        float4 a1 = __ldg(sp + 1);
                        float wgt = wq[s];
                        u0.x += wgt * a0.x; u0.y += wgt * a0.y;
                        u0.z += wgt * a0.z; u0.w += wgt * a0.w;
                        u1.x += wgt * a1.x; u1.y += wgt * a1.y;
                        u1.z += wgt * a1.z; u1.w += wgt * a1.w;
                    }
                }
                float* d = sval + cb * 136 + p;
                d[0 * 136] = to_tf32(u0.x); d[1 * 136] = to_tf32(u0.y);
                d[2 * 136] = to_tf32(u0.z); d[3 * 136] = to_tf32(u0.w);
                d[4 * 136] = to_tf32(u1.x); d[5 * 136] = to_tf32(u1.y);
                d[6 * 136] = to_tf32(u1.z); d[7 * 136] = to_tf32(u1.w);
            }
        }
        __syncthreads();

        // GEMM: 8 k-steps of m16n8k8 over this tap's 64 channels
        #pragma unroll
        for (int k0 = 0; k0 < 64; k0 += 8) {
            uint32_t afr[2][4];
            #pragma unroll
            for (int mt = 0; mt < 2; ++mt) {
                int pxb = warp_m * 32 + mt * 16 + lq;
                afr[mt][0] = __float_as_uint(sval[(k0 + lr) * 136 + pxb]);
                afr[mt][1] = __float_as_uint(sval[(k0 + lr) * 136 + pxb + 8]);
                afr[mt][2] = __float_as_uint(sval[(k0 + lr + 4) * 136 + pxb]);
                afr[mt][3] = __float_as_uint(sval[(k0 + lr + 4) * 136 + pxb + 8]);
            }
            uint32_t bfr[4][2];
            #pragma unroll
            for (int nt = 0; nt < 4; ++nt) {
                int oc = warp_n * 32 + nt * 8 + lq;
                bfr[nt][0] = __float_as_uint(swk[oc * 68 + k0 + lr]);
                bfr[nt][1] = __float_as_uint(swk[oc * 68 + k0 + lr + 4]);
            }
            #pragma unroll
            for (int mt = 0; mt < 2; ++mt)
                #pragma unroll
                for (int nt = 0; nt < 4; ++nt)
                    mma8(acc[mt][nt], afr[mt], bfr[nt]);
        }
    }

    // epilogue: bias + LeakyReLU, transpose via smem, coalesced store
    __syncthreads();
    float* outs = sm;   // reuse [64 oc][136 px]
    #pragma unroll
    for (int mt = 0; mt < 2; ++mt) {
        #pragma unroll
        for (int nt = 0; nt < 4; ++nt) {
            int px = warp_m * 32 + mt * 16 + lq;
            int oc = warp_n * 32 + nt * 8 + 2 * lr;
            float b0 = __ldg(b_dc + oc), b1 = __ldg(b_dc + oc + 1);
            float4 v = acc[mt][nt];
            float e0 = v.x + b0, e1 = v.y + b1, e2 = v.z + b0, e3 = v.w + b1;
            e0 = e0 > 0.f ? e0 : 0.2f * e0;
            e1 = e1 > 0.f ? e1 : 0.2f * e1;
            e2 = e2 > 0.f ? e2 : 0.2f * e2;
            e3 = e3 > 0.f ? e3 : 0.2f * e3;
            outs[oc * 136 + px]           = e0;
            outs[(oc + 1) * 136 + px]     = e1;
            outs[oc * 136 + px + 8]       = e2;
            outs[(oc + 1) * 136 + px + 8] = e3;
        }
    }
    __syncthreads();
    #pragma unroll
    for (int j = 0; j < 8; ++j) {
        int idx = tid + 256 * j;
        int oc = idx >> 5, pxq = idx & 31;
        float4 v = *(const float4*)&outs[oc * 136 + pxq * 4];
        *(float4*)(g_act + ((size_t)b * CC + oc) * HWs + h * WW + pxq * 4) = v;
    }
}

// ---------------------------------------------------------------------------
// Kernel C: 3x3 conv 64->64 on act + bias + residual, tf32 tensor-core GEMM.
// Same skeleton; per tap loads a shifted act row (L2-resident) into sval.
// ---------------------------------------------------------------------------
#define C_SMEM_FLOATS (64*136 + 64*68)
__global__ __launch_bounds__(256, 2) void conv2_kernel(const float* __restrict__ x,
                                                       const float* __restrict__ w_c,
                                                       const float* __restrict__ b_c,
                                                       float* __restrict__ out) {
    extern __shared__ float sm[];
    float* sval = sm;              // [64][136]
    float* swk  = sm + 64 * 136;   // [64][68]

    int tid = threadIdx.x;
    int b = blockIdx.x >> 7;
    int h = blockIdx.x & 127;

    int lane = tid & 31, wid = tid >> 5;
    int warp_m = wid & 3;
    int warp_n = wid >> 2;
    int lq = lane >> 2, lr = lane & 3;

    float4 acc[2][4];
    #pragma unroll
    for (int mt = 0; mt < 2; ++mt)
        #pragma unroll
        for (int nt = 0; nt < 4; ++nt) acc[mt][nt] = make_float4(0.f, 0.f, 0.f, 0.f);

    #pragma unroll 1
    for (int tap = 0; tap < KK; ++tap) {
        int dy = tap / 3, dx = tap % 3;
        int y = h - 1 + dy;
        bool yok = (y >= 0) & (y < HH);

        __syncthreads();
        #pragma unroll
        for (int i = tid; i < 4096; i += 256) {
            int o = i >> 6, c = i & 63;
            swk[o * 68 + c] = to_tf32(__ldg(w_c + (size_t)o * CK + c * 9 + tap));
        }
        // sval[c][p] = act[b][c][y][p-1+dx]
        #pragma unroll 4
        for (int j = 0; j < 32; ++j) {
            int idx = tid + 256 * j;
            int c = idx >> 7, pp = idx & 127;
            int xg = pp - 1 + dx;
            float v = 0.f;
            if (yok && xg >= 0 && xg < WW)
                v = __ldg(g_act + ((size_t)b * CC + c) * HWs + y * WW + xg);
            sval[c * 136 + pp] = to_tf32(v);
        }
        __syncthreads();

        #pragma unroll
        for (int k0 = 0; k0 < 64; k0 += 8) {
            uint32_t afr[2][4];
            #pragma unroll
            for (int mt = 0; mt < 2; ++mt) {
                int pxb = warp_m * 32 + mt * 16 + lq;
                afr[mt][0] = __float_as_uint(sval[(k0 + lr) * 136 + pxb]);
                afr[mt][1] = __float_as_uint(sval[(k0 + lr) * 136 + pxb + 8]);
                afr[mt][2] = __float_as_uint(sval[(k0 + lr + 4) * 136 + pxb]);
                afr[mt][3] = __float_as_uint(sval[(k0 + lr + 4) * 136 + pxb + 8]);
            }
            uint32_t bfr[4][2];
            #pragma unroll
            for (int nt = 0; nt < 4; ++nt) {
                int oc = warp_n * 32 + nt * 8 + lq;
                bfr[nt][0] = __float_as_uint(swk[oc * 68 + k0 + lr]);
                bfr[nt][1] = __float_as_uint(swk[oc * 68 + k0 + lr + 4]);
            }
            #pragma unroll
            for (int mt = 0; mt < 2; ++mt)
                #pragma unroll
                for (int nt = 0; nt < 4; ++nt)
                    mma8(acc[mt][nt], afr[mt], bfr[nt]);
        }
    }

    // epilogue: bias, transpose via smem, residual + coalesced store
    __syncthreads();
    float* outs = sm;
    #pragma unroll
    for (int mt = 0; mt < 2; ++mt) {
        #pragma unroll
        for (int nt = 0; nt < 4; ++nt) {
            int px = warp_m * 32 + mt * 16 + lq;
            int oc = warp_n * 32 + nt * 8 + 2 * lr;
            float b0 = __ldg(b_c + oc), b1 = __ldg(b_c + oc + 1);
            float4 v = acc[mt][nt];
            outs[oc * 136 + px]           = v.x + b0;
            outs[(oc + 1) * 136 + px]     = v.y + b1;
            outs[oc * 136 + px + 8]       = v.z + b0;
            outs[(oc + 1) * 136 + px + 8] = v.w + b1;
        }
    }
    __syncthreads();
    #pragma unroll
    for (int j = 0; j < 8; ++j) {
        int idx = tid + 256 * j;
        int oc = idx >> 5, pxq = idx & 31;
        size_t base = ((size_t)b * CC + oc) * HWs + h * WW + pxq * 4;
        float4 v = *(const float4*)&outs[oc * 136 + pxq * 4];
        float4 r = *(const float4*)(x + base);
        v.x += r.x; v.y += r.y; v.z += r.z; v.w += r.w;
        *(float4*)(out + base) = v;
    }
}

// ---------------------------------------------------------------------------
extern "C" void kernel_launch(void* const* d_in, const int* in_sizes, int n_in,
                              void* d_out, int out_size) {
    const float* x    = (const float*)d_in[0];
    const float* w_om = (const float*)d_in[1];
    const float* b_om = (const float*)d_in[2];
    const float* w_dc = (const float*)d_in[3];
    const float* b_dc = (const float*)d_in[4];
    const float* w_c  = (const float*)d_in[5];
    const float* b_c  = (const float*)d_in[6];
    float* out = (float*)d_out;

    cudaFuncSetAttribute(offmask_kernel, cudaFuncAttributeMaxDynamicSharedMemorySize,
                         A_SMEM_FLOATS * (int)sizeof(float));
    cudaFuncSetAttribute(deform_kernel, cudaFuncAttributeMaxDynamicSharedMemorySize,
                         B_SMEM_FLOATS * (int)sizeof(float));
    cudaFuncSetAttribute(conv2_kernel, cudaFuncAttributeMaxDynamicSharedMemorySize,
                         C_SMEM_FLOATS * (int)sizeof(float));

    transpose_kernel<<<BB * (HWs / 64), 256>>>(x);

    dim3 gridA(WW / 16, HH / 16, BB);
    offmask_kernel<<<gridA, 256, A_SMEM_FLOATS * sizeof(float)>>>(x, w_om, b_om);

    deform_kernel<<<BB * HH, 256, B_SMEM_FLOATS * sizeof(float)>>>(w_dc, b_dc);

    conv2_kernel<<<BB * HH, 256, C_SMEM_FLOATS * sizeof(float)>>>(x, w_c, b_c, out);
}

// round 4
// speedup vs baseline: 3.0996x; 1.4986x over previous
#include <cuda_runtime.h>
#include <cstdint>
#include <math.h>

#define HH 128
#define WW 128
#define HWs (HH*WW)
#define CC 64
#define BB 8
#define KK 9
#define CK 576

// Scratch (device globals: allocation-free kernel_launch)
__device__ float g_xnhwc[(size_t)BB * HWs * CC];     // NHWC copy of x
__device__ float g_offmask[(size_t)BB * HWs * 27];   // [b][pix][k][{offy,offx,mask}]
__device__ float g_act[(size_t)BB * CC * HWs];       // NCHW leaky output
__device__ float g_wdcT[9 * 64 * 64];                // [tap][oc][c], tf32
__device__ float g_wcT[9 * 64 * 64];                 // [tap][oc][c], tf32
__device__ float g_womT[9 * 32 * 64];                // [tap][oc(27 pad32)][c], tf32

// ---------------------------------------------------------------------------
__device__ __forceinline__ float to_tf32(float f) {
    uint32_t u;
    asm("cvt.rna.tf32.f32 %0, %1;" : "=r"(u) : "f"(f));
    return __uint_as_float(u);
}

__device__ __forceinline__ void mma8(float4& d, const uint32_t* a, const uint32_t* bf) {
    asm volatile(
        "mma.sync.aligned.m16n8k8.row.col.f32.tf32.tf32.f32 "
        "{%0,%1,%2,%3},{%4,%5,%6,%7},{%8,%9},{%0,%1,%2,%3};\n"
        : "+f"(d.x), "+f"(d.y), "+f"(d.z), "+f"(d.w)
        : "r"(a[0]), "r"(a[1]), "r"(a[2]), "r"(a[3]), "r"(bf[0]), "r"(bf[1]));
}

// ---------------------------------------------------------------------------
// Kernel W: pre-transpose weights to [tap][oc][c] (tf32)
// ---------------------------------------------------------------------------
__global__ __launch_bounds__(256) void wtrans_kernel(const float* __restrict__ w_dc,
                                                     const float* __restrict__ w_c,
                                                     const float* __restrict__ w_om) {
    int i = blockIdx.x * 256 + threadIdx.x;
    if (i < 36864) {
        int tap = i >> 12, rem = i & 4095, o = rem >> 6, c = rem & 63;
        g_wdcT[i] = to_tf32(w_dc[o * 576 + c * 9 + tap]);
    } else if (i < 73728) {
        int j = i - 36864;
        int tap = j >> 12, rem = j & 4095, o = rem >> 6, c = rem & 63;
        g_wcT[j] = to_tf32(w_c[o * 576 + c * 9 + tap]);
    } else if (i < 92160) {
        int j = i - 73728;
        int tap = j >> 11, rem = j & 2047, o = rem >> 6, c = rem & 63;
        g_womT[j] = (o < 27) ? to_tf32(w_om[o * 576 + c * 9 + tap]) : 0.f;
    }
}

// ---------------------------------------------------------------------------
// Kernel T: NCHW -> NHWC transpose
// ---------------------------------------------------------------------------
__global__ __launch_bounds__(256) void transpose_kernel(const float* __restrict__ x) {
    __shared__ float t[64 * 65];
    int tid = threadIdx.x;
    int blk = blockIdx.x;
    int b  = blk >> 8;
    int p0 = (blk & 255) * 64;

    #pragma unroll
    for (int i = tid; i < 4096; i += 256) {
        int c  = i >> 6;
        int pl = i & 63;
        t[pl * 65 + c] = x[((size_t)b * CC + c) * HWs + p0 + pl];
    }
    __syncthreads();
    #pragma unroll
    for (int i = tid; i < 4096; i += 256) {
        int pl = i >> 6;
        int c  = i & 63;
        g_xnhwc[((size_t)b * HWs + p0 + pl) * CC + c] = t[pl * 65 + c];
    }
}

// ---------------------------------------------------------------------------
// Kernel A: offsets+mask conv via tf32 tensor cores. Block = one row (128 px).
// Per dy: load x row once; 3 taps (dx shifts) of MMA; weights double-buffered.
// N = 32 (27 used). Epilogue: bias, 2*sigmoid(mask), interleaved store.
// ---------------------------------------------------------------------------
#define OM_SMEM_FLOATS (64*136 + 2*32*68)
__global__ __launch_bounds__(256, 2) void offmask_tc(const float* __restrict__ x,
                                                     const float* __restrict__ b_om) {
    extern __shared__ float sm[];
    float* sval = sm;              // [64][136]
    float* swk  = sm + 64 * 136;   // [2][32][68]

    int tid = threadIdx.x;
    int b = blockIdx.x >> 7;
    int h = blockIdx.x & 127;

    int lane = tid & 31, wid = tid >> 5;
    int warp_m = wid & 3;
    int warp_n = wid >> 2;         // 0..1 -> 16 oc each
    int lq = lane >> 2, lr = lane & 3;

    float4 acc[2][2];
    #pragma unroll
    for (int mt = 0; mt < 2; ++mt)
        #pragma unroll
        for (int nt = 0; nt < 2; ++nt) acc[mt][nt] = make_float4(0.f, 0.f, 0.f, 0.f);

    // preload tap0 weights into buf0 (512 float4)
    #pragma unroll
    for (int r = 0; r < 2; ++r) {
        int idx = tid + 256 * r;
        int o = idx >> 4, cq = idx & 15;
        *(float4*)&swk[o * 68 + cq * 4] = *(const float4*)&g_womT[idx * 4];
    }

    #pragma unroll 1
    for (int dy = 0; dy < 3; ++dy) {
        if (dy) __syncthreads();   // prior MMA done reading sval
        int y = h - 1 + dy;
        bool yok = (y >= 0) & (y < HH);
        const float* xrow = x + (size_t)b * CC * HWs + (size_t)y * WW;
        // sval[c][j] = x[b][c][y][j-1]
        {
            int ch = tid >> 7, j = tid & 127;
            int xg = j - 1;
            #pragma unroll
            for (int c0 = 0; c0 < 64; c0 += 2) {
                int c = c0 + ch;
                float v = (yok && xg >= 0) ? __ldg(xrow + (size_t)c * HWs + xg) : 0.f;
                sval[c * 136 + j] = to_tf32(v);
            }
            if (tid < 128) {
                int c = tid >> 1, jj = 128 + (tid & 1);
                float v = (yok && jj < 129) ? __ldg(xrow + (size_t)c * HWs + jj - 1) : 0.f;
                sval[c * 136 + jj] = to_tf32(v);
            }
        }
        #pragma unroll
        for (int dx = 0; dx < 3; ++dx) {
            int t = dy * 3 + dx;
            __syncthreads();       // publish sval + weights buf t&1
            if (t < 8) {           // prefetch next tap's weights
                int nb = (t + 1) & 1;
                #pragma unroll
                for (int r = 0; r < 2; ++r) {
                    int idx = tid + 256 * r;
                    int o = idx >> 4, cq = idx & 15;
                    *(float4*)&swk[nb * 2176 + o * 68 + cq * 4] =
                        *(const float4*)&g_womT[(t + 1) * 2048 + idx * 4];
                }
            }
            const float* wb = swk + (t & 1) * 2176;
            #pragma unroll
            for (int k0 = 0; k0 < 64; k0 += 8) {
                uint32_t afr[2][4];
                #pragma unroll
                for (int mt = 0; mt < 2; ++mt) {
                    int pxb = warp_m * 32 + mt * 16 + lq + dx;
                    afr[mt][0] = __float_as_uint(sval[(k0 + lr) * 136 + pxb]);
                    afr[mt][1] = __float_as_uint(sval[(k0 + lr) * 136 + pxb + 8]);
                    afr[mt][2] = __float_as_uint(sval[(k0 + lr + 4) * 136 + pxb]);
                    afr[mt][3] = __float_as_uint(sval[(k0 + lr + 4) * 136 + pxb + 8]);
                }
                uint32_t bfr[2][2];
                #pragma unroll
                for (int nt = 0; nt < 2; ++nt) {
                    int oc = warp_n * 16 + nt * 8 + lq;
                    bfr[nt][0] = __float_as_uint(wb[oc * 68 + k0 + lr]);
                    bfr[nt][1] = __float_as_uint(wb[oc * 68 + k0 + lr + 4]);
                }
                #pragma unroll
                for (int mt = 0; mt < 2; ++mt)
                    #pragma unroll
                    for (int nt = 0; nt < 2; ++nt)
                        mma8(acc[mt][nt], afr[mt], bfr[nt]);
            }
        }
    }

    // epilogue
    __syncthreads();
    float* outs = sm;   // [32 oc][136 px]
    #pragma unroll
    for (int mt = 0; mt < 2; ++mt) {
        #pragma unroll
        for (int nt = 0; nt < 2; ++nt) {
            int px = warp_m * 32 + mt * 16 + lq;
            int oc = warp_n * 16 + nt * 8 + 2 * lr;
            float4 v = acc[mt][nt];
            outs[oc * 136 + px]           = v.x;
            outs[(oc + 1) * 136 + px]     = v.y;
            outs[oc * 136 + px + 8]       = v.z;
            outs[(oc + 1) * 136 + px + 8] = v.w;
        }
    }
    __syncthreads();
    float* dst = g_offmask + ((size_t)b * HWs + h * WW) * 27;
    for (int idx = tid; idx < 128 * 27; idx += 256) {
        int px = idx / 27, e = idx - px * 27;
        int k = e / 3, r = e - 3 * k;
        int src = (r < 2) ? (2 * k + r) : (18 + k);
        float v = outs[src * 136 + px] + __ldg(b_om + src);
        if (r == 2) v = 2.f / (1.f + expf(-v));
        dst[px * 27 + e] = v;
    }
}

// ---------------------------------------------------------------------------
// Kernel B: modulated deformable conv 64->64, tf32 tensor-core GEMM.
// Per tap: coalesced weight copy + bilinear gather -> sval, then 8 k-steps MMA.
// ---------------------------------------------------------------------------
#define B_SMEM_FLOATS (64*136 + 64*68)
__global__ __launch_bounds__(256, 2) void deform_kernel(const float* __restrict__ b_dc) {
    extern __shared__ float sm[];
    float* sval = sm;              // [64][136]
    float* swk  = sm + 64 * 136;   // [64][68]

    int tid = threadIdx.x;
    int b = blockIdx.x >> 7;
    int h = blockIdx.x & 127;

    int lane = tid & 31, wid = tid >> 5;
    int warp_m = wid & 3;
    int warp_n = wid >> 2;
    int lq = lane >> 2, lr = lane & 3;

    int p     = tid & 127;
    int half_ = tid >> 7;
    const float* om = g_offmask + ((size_t)b * HWs + h * WW + p) * 27;
    const float* xb = g_xnhwc + (size_t)b * HWs * CC;

    float4 acc[2][4];
    #pragma unroll
    for (int mt = 0; mt < 2; ++mt)
        #pragma unroll
        for (int nt = 0; nt < 4; ++nt) acc[mt][nt] = make_float4(0.f, 0.f, 0.f, 0.f);

    #pragma unroll 1
    for (int tap = 0; tap < KK; ++tap) {
        __syncthreads();
        // coalesced weight copy: [64][64] -> swk[64][68]
        #pragma unroll
        for (int r = 0; r < 4; ++r) {
            int idx = tid + 256 * r;
            int o = idx >> 4, cq = idx & 15;
            *(float4*)&swk[o * 68 + cq * 4] =
                *(const float4*)&g_wdcT[tap * 4096 + idx * 4];
        }
        // gather: channels [half_*32, +32) of pixel p for this tap
        {
            float offy = __ldg(om + tap * 3 + 0);
            float offx = __ldg(om + tap * 3 + 1);
            float msk  = __ldg(om + tap * 3 + 2);
            float py = (float)(h - 1 + tap / 3) + offy;
            float px = (float)(p - 1 + tap % 3) + offx;
            float y0f = floorf(py), x0f = floorf(px);
            float ly = py - y0f, lx = px - x0f;
            int y0 = (int)y0f, x0 = (int)x0f;

            float wq[4] = {(1.f - ly) * (1.f - lx) * msk,
                           (1.f - ly) * lx * msk,
                           ly * (1.f - lx) * msk,
                           ly * lx * msk};
            int ys[4] = {y0, y0, y0 + 1, y0 + 1};
            int xs[4] = {x0, x0 + 1, x0, x0 + 1};
            bool vd[4];
            int addr[4];
            #pragma unroll
            for (int s = 0; s < 4; ++s) {
                vd[s] = (ys[s] >= 0) & (ys[s] < HH) & (xs[s] >= 0) & (xs[s] < WW);
                addr[s] = (ys[s] * WW + xs[s]) * CC;
            }

            #pragma unroll
            for (int q = 0; q < 4; ++q) {
                int cb = half_ * 32 + q * 8;
                float4 u0 = make_float4(0.f, 0.f, 0.f, 0.f);
                float4 u1 = make_float4(0.f, 0.f, 0.f, 0.f);
                #pragma unroll
                for (int s = 0; s < 4; ++s) {
                    if (vd[s]) {
                        const float4* sp = (const float4*)(xb + addr[s] + cb);
                        float4 a0 = __ldg(sp);
                        float4 a1 = __ldg(sp + 1);
                        float wgt = wq[s];
                        u0.x += wgt * a0.x; u0.y += wgt * a0.y;
                        u0.z += wgt * a0.z; u0.w += wgt * a0.w;
                        u1.x += wgt * a1.x; u1.y += wgt * a1.y;
                        u1.z += wgt * a1.z; u1.w += wgt * a1.w;
                    }
                }
                float* d = sval + cb * 136 + p;
                d[0 * 136] = to_tf32(u0.x); d[1 * 136] = to_tf32(u0.y);
                d[2 * 136] = to_tf32(u0.z); d[3 * 136] = to_tf32(u0.w);
                d[4 * 136] = to_tf32(u1.x); d[5 * 136] = to_tf32(u1.y);
                d[6 * 136] = to_tf32(u1.z); d[7 * 136] = to_tf32(u1.w);
            }
        }
        __syncthreads();

        #pragma unroll
        for (int k0 = 0; k0 < 64; k0 += 8) {
            uint32_t afr[2][4];
            #pragma unroll
            for (int mt = 0; mt < 2; ++mt) {
                int pxb = warp_m * 32 + mt * 16 + lq;
                afr[mt][0] = __float_as_uint(sval[(k0 + lr) * 136 + pxb]);
                afr[mt][1] = __float_as_uint(sval[(k0 + lr) * 136 + pxb + 8]);
                afr[mt][2] = __float_as_uint(sval[(k0 + lr + 4) * 136 + pxb]);
                afr[mt][3] = __float_as_uint(sval[(k0 + lr + 4) * 136 + pxb + 8]);
            }
            uint32_t bfr[4][2];
            #pragma unroll
            for (int nt = 0; nt < 4; ++nt) {
                int oc = warp_n * 32 + nt * 8 + lq;
                bfr[nt][0] = __float_as_uint(swk[oc * 68 + k0 + lr]);
                bfr[nt][1] = __float_as_uint(swk[oc * 68 + k0 + lr + 4]);
            }
            #pragma unroll
            for (int mt = 0; mt < 2; ++mt)
                #pragma unroll
                for (int nt = 0; nt < 4; ++nt)
                    mma8(acc[mt][nt], afr[mt], bfr[nt]);
        }
    }

    // epilogue: bias + LeakyReLU, transpose via smem, coalesced store
    __syncthreads();
    float* outs = sm;   // [64 oc][136 px]
    #pragma unroll
    for (int mt = 0; mt < 2; ++mt) {
        #pragma unroll
        for (int nt = 0; nt < 4; ++nt) {
            int px = warp_m * 32 + mt * 16 + lq;
            int oc = warp_n * 32 + nt * 8 + 2 * lr;
            float b0 = __ldg(b_dc + oc), b1 = __ldg(b_dc + oc + 1);
            float4 v = acc[mt][nt];
            float e0 = v.x + b0, e1 = v.y + b1, e2 = v.z + b0, e3 = v.w + b1;
            e0 = e0 > 0.f ? e0 : 0.2f * e0;
            e1 = e1 > 0.f ? e1 : 0.2f * e1;
            e2 = e2 > 0.f ? e2 : 0.2f * e2;
            e3 = e3 > 0.f ? e3 : 0.2f * e3;
            outs[oc * 136 + px]           = e0;
            outs[(oc + 1) * 136 + px]     = e1;
            outs[oc * 136 + px + 8]       = e2;
            outs[(oc + 1) * 136 + px + 8] = e3;
        }
    }
    __syncthreads();
    #pragma unroll
    for (int j = 0; j < 8; ++j) {
        int idx = tid + 256 * j;
        int oc = idx >> 5, pxq = idx & 31;
        float4 v = *(const float4*)&outs[oc * 136 + pxq * 4];
        *(float4*)(g_act + ((size_t)b * CC + oc) * HWs + h * WW + pxq * 4) = v;
    }
}

// ---------------------------------------------------------------------------
// Kernel C: 3x3 conv 64->64 on act + bias + residual, tf32 tensor cores.
// Per dy: load act row once; 3 dx taps via shifted A columns; weights
// double-buffered (prefetch during MMA).
// ---------------------------------------------------------------------------
#define C_SMEM_FLOATS (64*136 + 2*64*68)
__global__ __launch_bounds__(256, 2) void conv2_kernel(const float* __restrict__ x,
                                                       const float* __restrict__ b_c,
                                                       float* __restrict__ out) {
    extern __shared__ float sm[];
    float* sval = sm;              // [64][136]
    float* swk  = sm + 64 * 136;   // [2][64][68]

    int tid = threadIdx.x;
    int b = blockIdx.x >> 7;
    int h = blockIdx.x & 127;

    int lane = tid & 31, wid = tid >> 5;
    int warp_m = wid & 3;
    int warp_n = wid >> 2;
    int lq = lane >> 2, lr = lane & 3;

    float4 acc[2][4];
    #pragma unroll
    for (int mt = 0; mt < 2; ++mt)
        #pragma unroll
        for (int nt = 0; nt < 4; ++nt) acc[mt][nt] = make_float4(0.f, 0.f, 0.f, 0.f);

    // preload tap0 weights into buf0 (1024 float4)
    #pragma unroll
    for (int r = 0; r < 4; ++r) {
        int idx = tid + 256 * r;
        int o = idx >> 4, cq = idx & 15;
        *(float4*)&swk[o * 68 + cq * 4] = *(const float4*)&g_wcT[idx * 4];
    }

    #pragma unroll 1
    for (int dy = 0; dy < 3; ++dy) {
        if (dy) __syncthreads();
        int y = h - 1 + dy;
        bool yok = (y >= 0) & (y < HH);
        const float* arow = g_act + (size_t)b * CC * HWs + (size_t)y * WW;
        {
            int ch = tid >> 7, j = tid & 127;
            int xg = j - 1;
            #pragma unroll
            for (int c0 = 0; c0 < 64; c0 += 2) {
                int c = c0 + ch;
                float v = (yok && xg >= 0) ? __ldg(arow + (size_t)c * HWs + xg) : 0.f;
                sval[c * 136 + j] = to_tf32(v);
            }
            if (tid < 128) {
                int c = tid >> 1, jj = 128 + (tid & 1);
                float v = (yok && jj < 129) ? __ldg(arow + (size_t)c * HWs + jj - 1) : 0.f;
                sval[c * 136 + jj] = to_tf32(v);
            }
        }
        #pragma unroll
        for (int dx = 0; dx < 3; ++dx) {
            int t = dy * 3 + dx;
            __syncthreads();
            if (t < 8) {
                int nb = (t + 1) & 1;
                #pragma unroll
                for (int r = 0; r < 4; ++r) {
                    int idx = tid + 256 * r;
                    int o = idx >> 4, cq = idx & 15;
                    *(float4*)&swk[nb * 4352 + o * 68 + cq * 4] =
                        *(const float4*)&g_wcT[(t + 1) * 4096 + idx * 4];
                }
            }
            const float* wb = swk + (t & 1) * 4352;
            #pragma unroll
            for (int k0 = 0; k0 < 64; k0 += 8) {
                uint32_t afr[2][4];
                #pragma unroll
                for (int mt = 0; mt < 2; ++mt) {
                    int pxb = warp_m * 32 + mt * 16 + lq + dx;
                    afr[mt][0] = __float_as_uint(sval[(k0 + lr) * 136 + pxb]);
                    afr[mt][1] = __float_as_uint(sval[(k0 + lr) * 136 + pxb + 8]);
                    afr[mt][2] = __float_as_uint(sval[(k0 + lr + 4) * 136 + pxb]);
                    afr[mt][3] = __float_as_uint(sval[(k0 + lr + 4) * 136 + pxb + 8]);
                }
                uint32_t bfr[4][2];
                #pragma unroll
                for (int nt = 0; nt < 4; ++nt) {
                    int oc = warp_n * 32 + nt * 8 + lq;
                    bfr[nt][0] = __float_as_uint(wb[oc * 68 + k0 + lr]);
                    bfr[nt][1] = __float_as_uint(wb[oc * 68 + k0 + lr + 4]);
                }
                #pragma unroll
                for (int mt = 0; mt < 2; ++mt)
                    #pragma unroll
                    for (int nt = 0; nt < 4; ++nt)
                        mma8(acc[mt][nt], afr[mt], bfr[nt]);
            }
        }
    }

    // epilogue: bias, transpose via smem, residual + coalesced store
    __syncthreads();
    float* outs = sm;
    #pragma unroll
    for (int mt = 0; mt < 2; ++mt) {
        #pragma unroll
        for (int nt = 0; nt < 4; ++nt) {
            int px = warp_m * 32 + mt * 16 + lq;
            int oc = warp_n * 32 + nt * 8 + 2 * lr;
            float b0 = __ldg(b_c + oc), b1 = __ldg(b_c + oc + 1);
            float4 v = acc[mt][nt];
            outs[oc * 136 + px]           = v.x + b0;
            outs[(oc + 1) * 136 + px]     = v.y + b1;
            outs[oc * 136 + px + 8]       = v.z + b0;
            outs[(oc + 1) * 136 + px + 8] = v.w + b1;
        }
    }
    __syncthreads();
    #pragma unroll
    for (int j = 0; j < 8; ++j) {
        int idx = tid + 256 * j;
        int oc = idx >> 5, pxq = idx & 31;
        size_t base = ((size_t)b * CC + oc) * HWs + h * WW + pxq * 4;
        float4 v = *(const float4*)&outs[oc * 136 + pxq * 4];
        float4 r = *(const float4*)(x + base);
        v.x += r.x; v.y += r.y; v.z += r.z; v.w += r.w;
        *(float4*)(out + base) = v;
    }
}

// ---------------------------------------------------------------------------
extern "C" void kernel_launch(void* const* d_in, const int* in_sizes, int n_in,
                              void* d_out, int out_size) {
    const float* x    = (const float*)d_in[0];
    const float* w_om = (const float*)d_in[1];
    const float* b_om = (const float*)d_in[2];
    const float* w_dc = (const float*)d_in[3];
    const float* b_dc = (const float*)d_in[4];
    const float* w_c  = (const float*)d_in[5];
    const float* b_c  = (const float*)d_in[6];
    float* out = (float*)d_out;

    cudaFuncSetAttribute(offmask_tc, cudaFuncAttributeMaxDynamicSharedMemorySize,
                         OM_SMEM_FLOATS * (int)sizeof(float));
    cudaFuncSetAttribute(deform_kernel, cudaFuncAttributeMaxDynamicSharedMemorySize,
                         B_SMEM_FLOATS * (int)sizeof(float));
    cudaFuncSetAttribute(conv2_kernel, cudaFuncAttributeMaxDynamicSharedMemorySize,
                         C_SMEM_FLOATS * (int)sizeof(float));

    wtrans_kernel<<<360, 256>>>(w_dc, w_c, w_om);
    transpose_kernel<<<BB * (HWs / 64), 256>>>(x);

    offmask_tc<<<BB * HH, 256, OM_SMEM_FLOATS * sizeof(float)>>>(x, b_om);

    deform_kernel<<<BB * HH, 256, B_SMEM_FLOATS * sizeof(float)>>>(b_dc);

    conv2_kernel<<<BB * HH, 256, C_SMEM_FLOATS * sizeof(float)>>>(x, b_c, out);
}

// round 5
// speedup vs baseline: 4.0085x; 1.2932x over previous
#include <cuda_runtime.h>
#include <cstdint>
#include <math.h>

#define HH 128
#define WW 128
#define HWs (HH*WW)
#define CC 64
#define BB 8
#define KK 9
#define CK 576

// Scratch (device globals: allocation-free kernel_launch)
__device__ float g_xnhwc[(size_t)BB * HWs * CC];     // NHWC copy of x
__device__ float g_offmask[(size_t)BB * HWs * 27];   // [b][pix][k][{offy,offx,mask}]
__device__ float g_act[(size_t)BB * CC * HWs];       // NCHW leaky output
__device__ float g_wdcT[9 * 64 * 64];                // [tap][oc][c], tf32
__device__ float g_wcT[9 * 64 * 64];                 // [tap][oc][c], tf32
__device__ float g_womT[9 * 32 * 64];                // [tap][oc(27 pad32)][c], tf32

// ---------------------------------------------------------------------------
__device__ __forceinline__ float to_tf32(float f) {
    uint32_t u;
    asm("cvt.rna.tf32.f32 %0, %1;" : "=r"(u) : "f"(f));
    return __uint_as_float(u);
}

__device__ __forceinline__ void mma8(float4& d, const uint32_t* a, const uint32_t* bf) {
    asm volatile(
        "mma.sync.aligned.m16n8k8.row.col.f32.tf32.tf32.f32 "
        "{%0,%1,%2,%3},{%4,%5,%6,%7},{%8,%9},{%0,%1,%2,%3};\n"
        : "+f"(d.x), "+f"(d.y), "+f"(d.z), "+f"(d.w)
        : "r"(a[0]), "r"(a[1]), "r"(a[2]), "r"(a[3]), "r"(bf[0]), "r"(bf[1]));
}

// ---------------------------------------------------------------------------
// Kernel W: pre-transpose weights to [tap][oc][c] (tf32)
// ---------------------------------------------------------------------------
__global__ __launch_bounds__(256) void wtrans_kernel(const float* __restrict__ w_dc,
                                                     const float* __restrict__ w_c,
                                                     const float* __restrict__ w_om) {
    int i = blockIdx.x * 256 + threadIdx.x;
    if (i < 36864) {
        int tap = i >> 12, rem = i & 4095, o = rem >> 6, c = rem & 63;
        g_wdcT[i] = to_tf32(w_dc[o * 576 + c * 9 + tap]);
    } else if (i < 73728) {
        int j = i - 36864;
        int tap = j >> 12, rem = j & 4095, o = rem >> 6, c = rem & 63;
        g_wcT[j] = to_tf32(w_c[o * 576 + c * 9 + tap]);
    } else if (i < 92160) {
        int j = i - 73728;
        int tap = j >> 11, rem = j & 2047, o = rem >> 6, c = rem & 63;
        g_womT[j] = (o < 27) ? to_tf32(w_om[o * 576 + c * 9 + tap]) : 0.f;
    }
}

// ---------------------------------------------------------------------------
// Kernel T: NCHW -> NHWC transpose
// ---------------------------------------------------------------------------
__global__ __launch_bounds__(256) void transpose_kernel(const float* __restrict__ x) {
    __shared__ float t[64 * 65];
    int tid = threadIdx.x;
    int blk = blockIdx.x;
    int b  = blk >> 8;
    int p0 = (blk & 255) * 64;

    #pragma unroll
    for (int i = tid; i < 4096; i += 256) {
        int c  = i >> 6;
        int pl = i & 63;
        t[pl * 65 + c] = x[((size_t)b * CC + c) * HWs + p0 + pl];
    }
    __syncthreads();
    #pragma unroll
    for (int i = tid; i < 4096; i += 256) {
        int pl = i >> 6;
        int c  = i & 63;
        g_xnhwc[((size_t)b * HWs + p0 + pl) * CC + c] = t[pl * 65 + c];
    }
}

// ---------------------------------------------------------------------------
// Kernel A: offsets+mask conv via tf32 tensor cores. Block = one row (128 px).
// ---------------------------------------------------------------------------
#define OM_SMEM_FLOATS (64*136 + 2*32*68)
__global__ __launch_bounds__(256, 2) void offmask_tc(const float* __restrict__ x,
                                                     const float* __restrict__ b_om) {
    extern __shared__ float sm[];
    float* sval = sm;              // [64][136]
    float* swk  = sm + 64 * 136;   // [2][32][68]

    int tid = threadIdx.x;
    int b = blockIdx.x >> 7;
    int h = blockIdx.x & 127;

    int lane = tid & 31, wid = tid >> 5;
    int warp_m = wid & 3;
    int warp_n = wid >> 2;
    int lq = lane >> 2, lr = lane & 3;

    float4 acc[2][2];
    #pragma unroll
    for (int mt = 0; mt < 2; ++mt)
        #pragma unroll
        for (int nt = 0; nt < 2; ++nt) acc[mt][nt] = make_float4(0.f, 0.f, 0.f, 0.f);

    #pragma unroll
    for (int r = 0; r < 2; ++r) {
        int idx = tid + 256 * r;
        int o = idx >> 4, cq = idx & 15;
        *(float4*)&swk[o * 68 + cq * 4] = *(const float4*)&g_womT[idx * 4];
    }

    #pragma unroll 1
    for (int dy = 0; dy < 3; ++dy) {
        if (dy) __syncthreads();
        int y = h - 1 + dy;
        bool yok = (y >= 0) & (y < HH);
        const float* xrow = x + (size_t)b * CC * HWs + (size_t)y * WW;
        {
            int ch = tid >> 7, j = tid & 127;
            int xg = j - 1;
            #pragma unroll
            for (int c0 = 0; c0 < 64; c0 += 2) {
                int c = c0 + ch;
                float v = (yok && xg >= 0) ? __ldg(xrow + (size_t)c * HWs + xg) : 0.f;
                sval[c * 136 + j] = to_tf32(v);
            }
            if (tid < 128) {
                int c = tid >> 1, jj = 128 + (tid & 1);
                float v = (yok && jj < 129) ? __ldg(xrow + (size_t)c * HWs + jj - 1) : 0.f;
                sval[c * 136 + jj] = to_tf32(v);
            }
        }
        #pragma unroll
        for (int dx = 0; dx < 3; ++dx) {
            int t = dy * 3 + dx;
            __syncthreads();
            if (t < 8) {
                int nb = (t + 1) & 1;
                #pragma unroll
                for (int r = 0; r < 2; ++r) {
                    int idx = tid + 256 * r;
                    int o = idx >> 4, cq = idx & 15;
                    *(float4*)&swk[nb * 2176 + o * 68 + cq * 4] =
                        *(const float4*)&g_womT[(t + 1) * 2048 + idx * 4];
                }
            }
            const float* wb = swk + (t & 1) * 2176;
            #pragma unroll
            for (int k0 = 0; k0 < 64; k0 += 8) {
                uint32_t afr[2][4];
                #pragma unroll
                for (int mt = 0; mt < 2; ++mt) {
                    int pxb = warp_m * 32 + mt * 16 + lq + dx;
                    afr[mt][0] = __float_as_uint(sval[(k0 + lr) * 136 + pxb]);
                    afr[mt][1] = __float_as_uint(sval[(k0 + lr) * 136 + pxb + 8]);
                    afr[mt][2] = __float_as_uint(sval[(k0 + lr + 4) * 136 + pxb]);
                    afr[mt][3] = __float_as_uint(sval[(k0 + lr + 4) * 136 + pxb + 8]);
                }
                uint32_t bfr[2][2];
                #pragma unroll
                for (int nt = 0; nt < 2; ++nt) {
                    int oc = warp_n * 16 + nt * 8 + lq;
                    bfr[nt][0] = __float_as_uint(wb[oc * 68 + k0 + lr]);
                    bfr[nt][1] = __float_as_uint(wb[oc * 68 + k0 + lr + 4]);
                }
                #pragma unroll
                for (int mt = 0; mt < 2; ++mt)
                    #pragma unroll
                    for (int nt = 0; nt < 2; ++nt)
                        mma8(acc[mt][nt], afr[mt], bfr[nt]);
            }
        }
    }

    __syncthreads();
    float* outs = sm;
    #pragma unroll
    for (int mt = 0; mt < 2; ++mt) {
        #pragma unroll
        for (int nt = 0; nt < 2; ++nt) {
            int px = warp_m * 32 + mt * 16 + lq;
            int oc = warp_n * 16 + nt * 8 + 2 * lr;
            float4 v = acc[mt][nt];
            outs[oc * 136 + px]           = v.x;
            outs[(oc + 1) * 136 + px]     = v.y;
            outs[oc * 136 + px + 8]       = v.z;
            outs[(oc + 1) * 136 + px + 8] = v.w;
        }
    }
    __syncthreads();
    float* dst = g_offmask + ((size_t)b * HWs + h * WW) * 27;
    for (int idx = tid; idx < 128 * 27; idx += 256) {
        int px = idx / 27, e = idx - px * 27;
        int k = e / 3, r = e - 3 * k;
        int src = (r < 2) ? (2 * k + r) : (18 + k);
        float v = outs[src * 136 + px] + __ldg(b_om + src);
        if (r == 2) v = 2.f / (1.f + expf(-v));
        dst[px * 27 + e] = v;
    }
}

// ---------------------------------------------------------------------------
// Kernel B: modulated deformable conv 64->64, tf32 tensor cores.
// Gather remapped: 16 lanes = 16 channel-quads of ONE pixel (line-sharing
// LDG.128s, 4 lines/instr instead of 32). sval is row-major A [128px][68].
// Offsets staged in smem. Per tap: weights copy + gather + 8 k-step MMA.
// ---------------------------------------------------------------------------
#define B_SMEM_FLOATS (128*68 + 64*68 + 128*27)
__global__ __launch_bounds__(256, 2) void deform_kernel(const float* __restrict__ b_dc) {
    extern __shared__ float sm[];
    float* sval = sm;                    // [128 px][68]  (row-major A)
    float* swk  = sm + 128 * 68;         // [64 oc][68]
    float* soff = swk + 64 * 68;         // [128 px][27]

    int tid = threadIdx.x;
    int b = blockIdx.x >> 7;
    int h = blockIdx.x & 127;

    int lane = tid & 31, wid = tid >> 5;
    int warp_m = wid & 3;
    int warp_n = wid >> 2;
    int lq = lane >> 2, lr = lane & 3;

    int csub = tid & 15;                 // channel quad (c = 4*csub)
    int psub = tid >> 4;                 // 0..15
    const float* xb = g_xnhwc + (size_t)b * HWs * CC;

    // stage offsets/mask row
    {
        const float* omrow = g_offmask + ((size_t)b * HWs + h * WW) * 27;
        #pragma unroll
        for (int i = tid; i < 128 * 27; i += 256) soff[i] = __ldg(omrow + i);
    }

    float4 acc[2][4];
    #pragma unroll
    for (int mt = 0; mt < 2; ++mt)
        #pragma unroll
        for (int nt = 0; nt < 4; ++nt) acc[mt][nt] = make_float4(0.f, 0.f, 0.f, 0.f);

    #pragma unroll 1
    for (int tap = 0; tap < KK; ++tap) {
        __syncthreads();   // prev MMA done reading sval (tap0: soff staged)
        // weight copy: [64][64] -> swk[64][68]
        #pragma unroll
        for (int r = 0; r < 4; ++r) {
            int idx = tid + 256 * r;
            int o = idx >> 4, cq = idx & 15;
            *(float4*)&swk[o * 68 + cq * 4] =
                *(const float4*)&g_wdcT[tap * 4096 + idx * 4];
        }
        int ty = h - 1 + tap / 3;
        int txoff = tap % 3 - 1;
        // gather: 8 passes x 16 pixels, 16 lanes = channel quads
        #pragma unroll 2
        for (int pass = 0; pass < 8; ++pass) {
            int p = pass * 16 + psub;
            const float* o3 = soff + p * 27 + tap * 3;
            float offy = o3[0], offx = o3[1], msk = o3[2];
            float py = (float)ty + offy;
            float px = (float)(p + txoff) + offx;
            float y0f = floorf(py), x0f = floorf(px);
            float ly = py - y0f, lx = px - x0f;
            int y0 = (int)y0f, x0 = (int)x0f;
            float w00 = (1.f - ly) * (1.f - lx) * msk;
            float w01 = (1.f - ly) * lx * msk;
            float w10 = ly * (1.f - lx) * msk;
            float w11 = ly * lx * msk;

            bool x0ok = (x0 >= 0) & (x0 < WW);
            bool x1ok = (x0 + 1 >= 0) & (x0 + 1 < WW);
            float4 u = make_float4(0.f, 0.f, 0.f, 0.f);
            if (y0 >= 0 && y0 < HH) {
                const float* rowp = xb + (size_t)(y0 * WW) * CC + csub * 4;
                if (x0ok) {
                    float4 a = __ldg((const float4*)(rowp + x0 * CC));
                    u.x += w00 * a.x; u.y += w00 * a.y; u.z += w00 * a.z; u.w += w00 * a.w;
                }
                if (x1ok) {
                    float4 a = __ldg((const float4*)(rowp + (x0 + 1) * CC));
                    u.x += w01 * a.x; u.y += w01 * a.y; u.z += w01 * a.z; u.w += w01 * a.w;
                }
            }
            if (y0 + 1 >= 0 && y0 + 1 < HH) {
                const float* rowp = xb + (size_t)((y0 + 1) * WW) * CC + csub * 4;
                if (x0ok) {
                    float4 a = __ldg((const float4*)(rowp + x0 * CC));
                    u.x += w10 * a.x; u.y += w10 * a.y; u.z += w10 * a.z; u.w += w10 * a.w;
                }
                if (x1ok) {
                    float4 a = __ldg((const float4*)(rowp + (x0 + 1) * CC));
                    u.x += w11 * a.x; u.y += w11 * a.y; u.z += w11 * a.z; u.w += w11 * a.w;
                }
            }
            float4 t4;
            t4.x = to_tf32(u.x); t4.y = to_tf32(u.y);
            t4.z = to_tf32(u.z); t4.w = to_tf32(u.w);
            *(float4*)&sval[p * 68 + csub * 4] = t4;
        }
        __syncthreads();

        // MMA: A row-major [px][68], B [oc][68]
        #pragma unroll
        for (int k0 = 0; k0 < 64; k0 += 8) {
            uint32_t afr[2][4];
            #pragma unroll
            for (int mt = 0; mt < 2; ++mt) {
                int pxb = warp_m * 32 + mt * 16 + lq;
                afr[mt][0] = __float_as_uint(sval[pxb * 68 + k0 + lr]);
                afr[mt][1] = __float_as_uint(sval[(pxb + 8) * 68 + k0 + lr]);
                afr[mt][2] = __float_as_uint(sval[pxb * 68 + k0 + lr + 4]);
                afr[mt][3] = __float_as_uint(sval[(pxb + 8) * 68 + k0 + lr + 4]);
            }
            uint32_t bfr[4][2];
            #pragma unroll
            for (int nt = 0; nt < 4; ++nt) {
                int oc = warp_n * 32 + nt * 8 + lq;
                bfr[nt][0] = __float_as_uint(swk[oc * 68 + k0 + lr]);
                bfr[nt][1] = __float_as_uint(swk[oc * 68 + k0 + lr + 4]);
            }
            #pragma unroll
            for (int mt = 0; mt < 2; ++mt)
                #pragma unroll
                for (int nt = 0; nt < 4; ++nt)
                    mma8(acc[mt][nt], afr[mt], bfr[nt]);
        }
    }

    // epilogue: bias + LeakyReLU, transpose via smem, coalesced store
    __syncthreads();
    float* outs = sm;   // [64 oc][136 px] = 8704 floats (fits in sval region)
    #pragma unroll
    for (int mt = 0; mt < 2; ++mt) {
        #pragma unroll
        for (int nt = 0; nt < 4; ++nt) {
            int px = warp_m * 32 + mt * 16 + lq;
            int oc = warp_n * 32 + nt * 8 + 2 * lr;
            float b0 = __ldg(b_dc + oc), b1 = __ldg(b_dc + oc + 1);
            float4 v = acc[mt][nt];
            float e0 = v.x + b0, e1 = v.y + b1, e2 = v.z + b0, e3 = v.w + b1;
            e0 = e0 > 0.f ? e0 : 0.2f * e0;
            e1 = e1 > 0.f ? e1 : 0.2f * e1;
            e2 = e2 > 0.f ? e2 : 0.2f * e2;
            e3 = e3 > 0.f ? e3 : 0.2f * e3;
            outs[oc * 136 + px]           = e0;
            outs[(oc + 1) * 136 + px]     = e1;
            outs[oc * 136 + px + 8]       = e2;
            outs[(oc + 1) * 136 + px + 8] = e3;
        }
    }
    __syncthreads();
    #pragma unroll
    for (int j = 0; j < 8; ++j) {
        int idx = tid + 256 * j;
        int oc = idx >> 5, pxq = idx & 31;
        float4 v = *(const float4*)&outs[oc * 136 + pxq * 4];
        *(float4*)(g_act + ((size_t)b * CC + oc) * HWs + h * WW + pxq * 4) = v;
    }
}

// ---------------------------------------------------------------------------
// Kernel C: 3x3 conv 64->64 on act + bias + residual, tf32 tensor cores.
// ---------------------------------------------------------------------------
#define C_SMEM_FLOATS (64*136 + 2*64*68)
__global__ __launch_bounds__(256, 2) void conv2_kernel(const float* __restrict__ x,
                                                       const float* __restrict__ b_c,
                                                       float* __restrict__ out) {
    extern __shared__ float sm[];
    float* sval = sm;              // [64][136]
    float* swk  = sm + 64 * 136;   // [2][64][68]

    int tid = threadIdx.x;
    int b = blockIdx.x >> 7;
    int h = blockIdx.x & 127;

    int lane = tid & 31, wid = tid >> 5;
    int warp_m = wid & 3;
    int warp_n = wid >> 2;
    int lq = lane >> 2, lr = lane & 3;

    float4 acc[2][4];
    #pragma unroll
    for (int mt = 0; mt < 2; ++mt)
        #pragma unroll
        for (int nt = 0; nt < 4; ++nt) acc[mt][nt] = make_float4(0.f, 0.f, 0.f, 0.f);

    #pragma unroll
    for (int r = 0; r < 4; ++r) {
        int idx = tid + 256 * r;
        int o = idx >> 4, cq = idx & 15;
        *(float4*)&swk[o * 68 + cq * 4] = *(const float4*)&g_wcT[idx * 4];
    }

    #pragma unroll 1
    for (int dy = 0; dy < 3; ++dy) {
        if (dy) __syncthreads();
        int y = h - 1 + dy;
        bool yok = (y >= 0) & (y < HH);
        const float* arow = g_act + (size_t)b * CC * HWs + (size_t)y * WW;
        {
            int ch = tid >> 7, j = tid & 127;
            int xg = j - 1;
            #pragma unroll
            for (int c0 = 0; c0 < 64; c0 += 2) {
                int c = c0 + ch;
                float v = (yok && xg >= 0) ? __ldg(arow + (size_t)c * HWs + xg) : 0.f;
                sval[c * 136 + j] = to_tf32(v);
            }
            if (tid < 128) {
                int c = tid >> 1, jj = 128 + (tid & 1);
                float v = (yok && jj < 129) ? __ldg(arow + (size_t)c * HWs + jj - 1) : 0.f;
                sval[c * 136 + jj] = to_tf32(v);
            }
        }
        #pragma unroll
        for (int dx = 0; dx < 3; ++dx) {
            int t = dy * 3 + dx;
            __syncthreads();
            if (t < 8) {
                int nb = (t + 1) & 1;
                #pragma unroll
                for (int r = 0; r < 4; ++r) {
                    int idx = tid + 256 * r;
                    int o = idx >> 4, cq = idx & 15;
                    *(float4*)&swk[nb * 4352 + o * 68 + cq * 4] =
                        *(const float4*)&g_wcT[(t + 1) * 4096 + idx * 4];
                }
            }
            const float* wb = swk + (t & 1) * 4352;
            #pragma unroll
            for (int k0 = 0; k0 < 64; k0 += 8) {
                uint32_t afr[2][4];
                #pragma unroll
                for (int mt = 0; mt < 2; ++mt) {
                    int pxb = warp_m * 32 + mt * 16 + lq + dx;
                    afr[mt][0] = __float_as_uint(sval[(k0 + lr) * 136 + pxb]);
                    afr[mt][1] = __float_as_uint(sval[(k0 + lr) * 136 + pxb + 8]);
                    afr[mt][2] = __float_as_uint(sval[(k0 + lr + 4) * 136 + pxb]);
                    afr[mt][3] = __float_as_uint(sval[(k0 + lr + 4) * 136 + pxb + 8]);
                }
                uint32_t bfr[4][2];
                #pragma unroll
                for (int nt = 0; nt < 4; ++nt) {
                    int oc = warp_n * 32 + nt * 8 + lq;
                    bfr[nt][0] = __float_as_uint(wb[oc * 68 + k0 + lr]);
                    bfr[nt][1] = __float_as_uint(wb[oc * 68 + k0 + lr + 4]);
                }
                #pragma unroll
                for (int mt = 0; mt < 2; ++mt)
                    #pragma unroll
                    for (int nt = 0; nt < 4; ++nt)
                        mma8(acc[mt][nt], afr[mt], bfr[nt]);
            }
        }
    }

    __syncthreads();
    float* outs = sm;
    #pragma unroll
    for (int mt = 0; mt < 2; ++mt) {
        #pragma unroll
        for (int nt = 0; nt < 4; ++nt) {
            int px = warp_m * 32 + mt * 16 + lq;
            int oc = warp_n * 32 + nt * 8 + 2 * lr;
            float b0 = __ldg(b_c + oc), b1 = __ldg(b_c + oc + 1);
            float4 v = acc[mt][nt];
            outs[oc * 136 + px]           = v.x + b0;
            outs[(oc + 1) * 136 + px]     = v.y + b1;
            outs[oc * 136 + px + 8]       = v.z + b0;
            outs[(oc + 1) * 136 + px + 8] = v.w + b1;
        }
    }
    __syncthreads();
    #pragma unroll
    for (int j = 0; j < 8; ++j) {
        int idx = tid + 256 * j;
        int oc = idx >> 5, pxq = idx & 31;
        size_t base = ((size_t)b * CC + oc) * HWs + h * WW + pxq * 4;
        float4 v = *(const float4*)&outs[oc * 136 + pxq * 4];
        float4 r = *(const float4*)(x + base);
        v.x += r.x; v.y += r.y; v.z += r.z; v.w += r.w;
        *(float4*)(out + base) = v;
    }
}

// ---------------------------------------------------------------------------
extern "C" void kernel_launch(void* const* d_in, const int* in_sizes, int n_in,
                              void* d_out, int out_size) {
    const float* x    = (const float*)d_in[0];
    const float* w_om = (const float*)d_in[1];
    const float* b_om = (const float*)d_in[2];
    const float* w_dc = (const float*)d_in[3];
    const float* b_dc = (const float*)d_in[4];
    const float* w_c  = (const float*)d_in[5];
    const float* b_c  = (const float*)d_in[6];
    float* out = (float*)d_out;

    cudaFuncSetAttribute(offmask_tc, cudaFuncAttributeMaxDynamicSharedMemorySize,
                         OM_SMEM_FLOATS * (int)sizeof(float));
    cudaFuncSetAttribute(deform_kernel, cudaFuncAttributeMaxDynamicSharedMemorySize,
                         B_SMEM_FLOATS * (int)sizeof(float));
    cudaFuncSetAttribute(conv2_kernel, cudaFuncAttributeMaxDynamicSharedMemorySize,
                         C_SMEM_FLOATS * (int)sizeof(float));

    wtrans_kernel<<<360, 256>>>(w_dc, w_c, w_om);
    transpose_kernel<<<BB * (HWs / 64), 256>>>(x);

    offmask_tc<<<BB * HH, 256, OM_SMEM_FLOATS * sizeof(float)>>>(x, b_om);

    deform_kernel<<<BB * HH, 256, B_SMEM_FLOATS * sizeof(float)>>>(b_dc);

    conv2_kernel<<<BB * HH, 256, C_SMEM_FLOATS * sizeof(float)>>>(x, b_c, out);
}

// round 6
// speedup vs baseline: 4.0731x; 1.0161x over previous
#include <cuda_runtime.h>
#include <cstdint>
#include <math.h>

#define HH 128
#define WW 128
#define HWs (HH*WW)
#define CC 64
#define BB 8
#define KK 9
#define CK 576

// Scratch (device globals: allocation-free kernel_launch)
__device__ float g_xnhwc[(size_t)BB * HWs * CC];     // NHWC copy of x
__device__ float g_offmask[(size_t)BB * HWs * 27];   // [b][pix][k][{offy,offx,mask}]
__device__ float g_act[(size_t)BB * CC * HWs];       // NCHW leaky output
__device__ float g_wdcT[9 * 64 * 64];                // [tap][oc][c], tf32
__device__ float g_wcT[9 * 64 * 64];                 // [tap][oc][c], tf32
__device__ float g_womT[9 * 32 * 64];                // [tap][oc(27 pad32)][c], tf32

// ---------------------------------------------------------------------------
__device__ __forceinline__ float to_tf32(float f) {
    uint32_t u;
    asm("cvt.rna.tf32.f32 %0, %1;" : "=r"(u) : "f"(f));
    return __uint_as_float(u);
}

__device__ __forceinline__ void mma8(float4& d, const uint32_t* a, const uint32_t* bf) {
    asm volatile(
        "mma.sync.aligned.m16n8k8.row.col.f32.tf32.tf32.f32 "
        "{%0,%1,%2,%3},{%4,%5,%6,%7},{%8,%9},{%0,%1,%2,%3};\n"
        : "+f"(d.x), "+f"(d.y), "+f"(d.z), "+f"(d.w)
        : "r"(a[0]), "r"(a[1]), "r"(a[2]), "r"(a[3]), "r"(bf[0]), "r"(bf[1]));
}

// ---------------------------------------------------------------------------
// Kernel W: pre-transpose weights to [tap][oc][c] (tf32)
// ---------------------------------------------------------------------------
__global__ __launch_bounds__(256) void wtrans_kernel(const float* __restrict__ w_dc,
                                                     const float* __restrict__ w_c,
                                                     const float* __restrict__ w_om) {
    int i = blockIdx.x * 256 + threadIdx.x;
    if (i < 36864) {
        int tap = i >> 12, rem = i & 4095, o = rem >> 6, c = rem & 63;
        g_wdcT[i] = to_tf32(w_dc[o * 576 + c * 9 + tap]);
    } else if (i < 73728) {
        int j = i - 36864;
        int tap = j >> 12, rem = j & 4095, o = rem >> 6, c = rem & 63;
        g_wcT[j] = to_tf32(w_c[o * 576 + c * 9 + tap]);
    } else if (i < 92160) {
        int j = i - 73728;
        int tap = j >> 11, rem = j & 2047, o = rem >> 6, c = rem & 63;
        g_womT[j] = (o < 27) ? to_tf32(w_om[o * 576 + c * 9 + tap]) : 0.f;
    }
}

// ---------------------------------------------------------------------------
// Kernel T: NCHW -> NHWC transpose
// ---------------------------------------------------------------------------
__global__ __launch_bounds__(256) void transpose_kernel(const float* __restrict__ x) {
    __shared__ float t[64 * 65];
    int tid = threadIdx.x;
    int blk = blockIdx.x;
    int b  = blk >> 8;
    int p0 = (blk & 255) * 64;

    #pragma unroll
    for (int i = tid; i < 4096; i += 256) {
        int c  = i >> 6;
        int pl = i & 63;
        t[pl * 65 + c] = x[((size_t)b * CC + c) * HWs + p0 + pl];
    }
    __syncthreads();
    #pragma unroll
    for (int i = tid; i < 4096; i += 256) {
        int pl = i >> 6;
        int c  = i & 63;
        g_xnhwc[((size_t)b * HWs + p0 + pl) * CC + c] = t[pl * 65 + c];
    }
}

// ---------------------------------------------------------------------------
// Kernel A: offsets+mask conv via tf32 tensor cores. Block = one row (128 px).
// ---------------------------------------------------------------------------
#define OM_SMEM_FLOATS (64*136 + 2*32*68)
__global__ __launch_bounds__(256, 2) void offmask_tc(const float* __restrict__ x,
                                                     const float* __restrict__ b_om) {
    extern __shared__ float sm[];
    float* sval = sm;              // [64][136]
    float* swk  = sm + 64 * 136;   // [2][32][68]

    int tid = threadIdx.x;
    int b = blockIdx.x >> 7;
    int h = blockIdx.x & 127;

    int lane = tid & 31, wid = tid >> 5;
    int warp_m = wid & 3;
    int warp_n = wid >> 2;
    int lq = lane >> 2, lr = lane & 3;

    float4 acc[2][2];
    #pragma unroll
    for (int mt = 0; mt < 2; ++mt)
        #pragma unroll
        for (int nt = 0; nt < 2; ++nt) acc[mt][nt] = make_float4(0.f, 0.f, 0.f, 0.f);

    #pragma unroll
    for (int r = 0; r < 2; ++r) {
        int idx = tid + 256 * r;
        int o = idx >> 4, cq = idx & 15;
        *(float4*)&swk[o * 68 + cq * 4] = *(const float4*)&g_womT[idx * 4];
    }

    #pragma unroll 1
    for (int dy = 0; dy < 3; ++dy) {
        if (dy) __syncthreads();
        int y = h - 1 + dy;
        bool yok = (y >= 0) & (y < HH);
        const float* xrow = x + (size_t)b * CC * HWs + (size_t)y * WW;
        {
            int ch = tid >> 7, j = tid & 127;
            int xg = j - 1;
            #pragma unroll
            for (int c0 = 0; c0 < 64; c0 += 2) {
                int c = c0 + ch;
                float v = (yok && xg >= 0) ? __ldg(xrow + (size_t)c * HWs + xg) : 0.f;
                sval[c * 136 + j] = to_tf32(v);
            }
            if (tid < 128) {
                int c = tid >> 1, jj = 128 + (tid & 1);
                float v = (yok && jj < 129) ? __ldg(xrow + (size_t)c * HWs + jj - 1) : 0.f;
                sval[c * 136 + jj] = to_tf32(v);
            }
        }
        #pragma unroll
        for (int dx = 0; dx < 3; ++dx) {
            int t = dy * 3 + dx;
            __syncthreads();
            if (t < 8) {
                int nb = (t + 1) & 1;
                #pragma unroll
                for (int r = 0; r < 2; ++r) {
                    int idx = tid + 256 * r;
                    int o = idx >> 4, cq = idx & 15;
                    *(float4*)&swk[nb * 2176 + o * 68 + cq * 4] =
                        *(const float4*)&g_womT[(t + 1) * 2048 + idx * 4];
                }
            }
            const float* wb = swk + (t & 1) * 2176;
            #pragma unroll
            for (int k0 = 0; k0 < 64; k0 += 8) {
                uint32_t afr[2][4];
                #pragma unroll
                for (int mt = 0; mt < 2; ++mt) {
                    int pxb = warp_m * 32 + mt * 16 + lq + dx;
                    afr[mt][0] = __float_as_uint(sval[(k0 + lr) * 136 + pxb]);
                    afr[mt][1] = __float_as_uint(sval[(k0 + lr) * 136 + pxb + 8]);
                    afr[mt][2] = __float_as_uint(sval[(k0 + lr + 4) * 136 + pxb]);
                    afr[mt][3] = __float_as_uint(sval[(k0 + lr + 4) * 136 + pxb + 8]);
                }
                uint32_t bfr[2][2];
                #pragma unroll
                for (int nt = 0; nt < 2; ++nt) {
                    int oc = warp_n * 16 + nt * 8 + lq;
                    bfr[nt][0] = __float_as_uint(wb[oc * 68 + k0 + lr]);
                    bfr[nt][1] = __float_as_uint(wb[oc * 68 + k0 + lr + 4]);
                }
                #pragma unroll
                for (int mt = 0; mt < 2; ++mt)
                    #pragma unroll
                    for (int nt = 0; nt < 2; ++nt)
                        mma8(acc[mt][nt], afr[mt], bfr[nt]);
            }
        }
    }

    __syncthreads();
    float* outs = sm;
    #pragma unroll
    for (int mt = 0; mt < 2; ++mt) {
        #pragma unroll
        for (int nt = 0; nt < 2; ++nt) {
            int px = warp_m * 32 + mt * 16 + lq;
            int oc = warp_n * 16 + nt * 8 + 2 * lr;
            float4 v = acc[mt][nt];
            outs[oc * 136 + px]           = v.x;
            outs[(oc + 1) * 136 + px]     = v.y;
            outs[oc * 136 + px + 8]       = v.z;
            outs[(oc + 1) * 136 + px + 8] = v.w;
        }
    }
    __syncthreads();
    float* dst = g_offmask + ((size_t)b * HWs + h * WW) * 27;
    for (int idx = tid; idx < 128 * 27; idx += 256) {
        int px = idx / 27, e = idx - px * 27;
        int k = e / 3, r = e - 3 * k;
        int src = (r < 2) ? (2 * k + r) : (18 + k);
        float v = outs[src * 136 + px] + __ldg(b_om + src);
        if (r == 2) v = 2.f / (1.f + expf(-v));
        dst[px * 27 + e] = v;
    }
}

// ---------------------------------------------------------------------------
// deform gather for one tap (this thread covers csub's channel-quad of
// 8 pixels). Writes tf32 to dst[p*68 + csub*4].
// ---------------------------------------------------------------------------
__device__ __forceinline__ void dgather(const float* __restrict__ xb,
                                        const float* __restrict__ omrow,
                                        float* __restrict__ dst,
                                        int h, int tap, int psub, int csub) {
    int ty = h - 1 + tap / 3;
    int txoff = tap % 3 - 1;
    #pragma unroll 4
    for (int pass = 0; pass < 8; ++pass) {
        int p = pass * 16 + psub;
        const float* o3 = omrow + p * 27 + tap * 3;
        float offy = __ldg(o3), offx = __ldg(o3 + 1), msk = __ldg(o3 + 2);
        float py = (float)ty + offy;
        float px = (float)(p + txoff) + offx;
        float y0f = floorf(py), x0f = floorf(px);
        float ly = py - y0f, lx = px - x0f;
        int y0 = (int)y0f, x0 = (int)x0f;
        float w00 = (1.f - ly) * (1.f - lx) * msk;
        float w01 = (1.f - ly) * lx * msk;
        float w10 = ly * (1.f - lx) * msk;
        float w11 = ly * lx * msk;

        bool x0ok = (x0 >= 0) & (x0 < WW);
        bool x1ok = (x0 + 1 >= 0) & (x0 + 1 < WW);
        float4 u = make_float4(0.f, 0.f, 0.f, 0.f);
        if (y0 >= 0 && y0 < HH) {
            const float* rowp = xb + (size_t)(y0 * WW) * CC + csub * 4;
            if (x0ok) {
                float4 a = __ldg((const float4*)(rowp + x0 * CC));
                u.x += w00 * a.x; u.y += w00 * a.y; u.z += w00 * a.z; u.w += w00 * a.w;
            }
            if (x1ok) {
                float4 a = __ldg((const float4*)(rowp + (x0 + 1) * CC));
                u.x += w01 * a.x; u.y += w01 * a.y; u.z += w01 * a.z; u.w += w01 * a.w;
            }
        }
        if (y0 + 1 >= 0 && y0 + 1 < HH) {
            const float* rowp = xb + (size_t)((y0 + 1) * WW) * CC + csub * 4;
            if (x0ok) {
                float4 a = __ldg((const float4*)(rowp + x0 * CC));
                u.x += w10 * a.x; u.y += w10 * a.y; u.z += w10 * a.z; u.w += w10 * a.w;
            }
            if (x1ok) {
                float4 a = __ldg((const float4*)(rowp + (x0 + 1) * CC));
                u.x += w11 * a.x; u.y += w11 * a.y; u.z += w11 * a.z; u.w += w11 * a.w;
            }
        }
        float4 t4;
        t4.x = to_tf32(u.x); t4.y = to_tf32(u.y);
        t4.z = to_tf32(u.z); t4.w = to_tf32(u.w);
        *(float4*)&dst[p * 68 + csub * 4] = t4;
    }
}

// ---------------------------------------------------------------------------
// Kernel B: modulated deformable conv 64->64, tf32 tensor cores,
// software-pipelined across taps: one sync/tap; MMA(t) overlaps gather(t+1)
// and weight prefetch(t+1). sval/swk double-buffered.
// ---------------------------------------------------------------------------
#define B_SMEM_FLOATS (2*128*68 + 2*64*68)
__global__ __launch_bounds__(256, 2) void deform_kernel(const float* __restrict__ b_dc) {
    extern __shared__ float sm[];
    float* sval = sm;                    // [2][128 px][68]
    float* swk  = sm + 2 * 128 * 68;     // [2][64 oc][68]

    int tid = threadIdx.x;
    int b = blockIdx.x >> 7;
    int h = blockIdx.x & 127;

    int lane = tid & 31, wid = tid >> 5;
    int warp_m = wid & 3;
    int warp_n = wid >> 2;
    int lq = lane >> 2, lr = lane & 3;

    int csub = tid & 15;                 // channel quad (c = 4*csub)
    int psub = tid >> 4;                 // 0..15
    const float* xb = g_xnhwc + (size_t)b * HWs * CC;
    const float* omrow = g_offmask + ((size_t)b * HWs + h * WW) * 27;

    int widx_o = tid >> 4, widx_c = tid & 15;   // weight copy mapping

    float4 acc[2][4];
    #pragma unroll
    for (int mt = 0; mt < 2; ++mt)
        #pragma unroll
        for (int nt = 0; nt < 4; ++nt) acc[mt][nt] = make_float4(0.f, 0.f, 0.f, 0.f);

    // prologue: tap0 weights + gather
    #pragma unroll
    for (int r = 0; r < 4; ++r) {
        int idx = tid + 256 * r;
        *(float4*)&swk[(idx >> 4) * 68 + (idx & 15) * 4] =
            *(const float4*)&g_wdcT[idx * 4];
    }
    dgather(xb, omrow, sval, h, 0, psub, csub);
    __syncthreads();

    #pragma unroll 1
    for (int tap = 0; tap < KK; ++tap) {
        int cur = tap & 1, nxt = cur ^ 1;
        bool pre = tap < 8;

        // prefetch next tap's weights into registers (LDG issues early)
        float4 wreg[4];
        if (pre) {
            #pragma unroll
            for (int r = 0; r < 4; ++r)
                wreg[r] = *(const float4*)&g_wdcT[(tap + 1) * 4096 + (tid + 256 * r) * 4];
        }

        // MMA(tap): A row-major sval[cur], B swk[cur]
        const float* sv = sval + cur * 128 * 68;
        const float* wb = swk + cur * 64 * 68;
        #pragma unroll
        for (int k0 = 0; k0 < 64; k0 += 8) {
            uint32_t afr[2][4];
            #pragma unroll
            for (int mt = 0; mt < 2; ++mt) {
                int pxb = warp_m * 32 + mt * 16 + lq;
                afr[mt][0] = __float_as_uint(sv[pxb * 68 + k0 + lr]);
                afr[mt][1] = __float_as_uint(sv[(pxb + 8) * 68 + k0 + lr]);
                afr[mt][2] = __float_as_uint(sv[pxb * 68 + k0 + lr + 4]);
                afr[mt][3] = __float_as_uint(sv[(pxb + 8) * 68 + k0 + lr + 4]);
            }
            uint32_t bfr[4][2];
            #pragma unroll
            for (int nt = 0; nt < 4; ++nt) {
                int oc = warp_n * 32 + nt * 8 + lq;
                bfr[nt][0] = __float_as_uint(wb[oc * 68 + k0 + lr]);
                bfr[nt][1] = __float_as_uint(wb[oc * 68 + k0 + lr + 4]);
            }
            #pragma unroll
            for (int mt = 0; mt < 2; ++mt)
                #pragma unroll
                for (int nt = 0; nt < 4; ++nt)
                    mma8(acc[mt][nt], afr[mt], bfr[nt]);
        }

        // gather next tap (LDG latency overlaps tensor pipe + other warps)
        if (pre) {
            dgather(xb, omrow, sval + nxt * 128 * 68, h, tap + 1, psub, csub);
            #pragma unroll
            for (int r = 0; r < 4; ++r) {
                int idx = tid + 256 * r;
                *(float4*)&swk[nxt * 64 * 68 + (idx >> 4) * 68 + (idx & 15) * 4] = wreg[r];
            }
        }
        __syncthreads();
    }

    // epilogue: bias + LeakyReLU, transpose via smem, coalesced store
    float* outs = sm;   // [64 oc][136 px] = 8704 floats
    #pragma unroll
    for (int mt = 0; mt < 2; ++mt) {
        #pragma unroll
        for (int nt = 0; nt < 4; ++nt) {
            int px = warp_m * 32 + mt * 16 + lq;
            int oc = warp_n * 32 + nt * 8 + 2 * lr;
            float b0 = __ldg(b_dc + oc), b1 = __ldg(b_dc + oc + 1);
            float4 v = acc[mt][nt];
            float e0 = v.x + b0, e1 = v.y + b1, e2 = v.z + b0, e3 = v.w + b1;
            e0 = e0 > 0.f ? e0 : 0.2f * e0;
            e1 = e1 > 0.f ? e1 : 0.2f * e1;
            e2 = e2 > 0.f ? e2 : 0.2f * e2;
            e3 = e3 > 0.f ? e3 : 0.2f * e3;
            outs[oc * 136 + px]           = e0;
            outs[(oc + 1) * 136 + px]     = e1;
            outs[oc * 136 + px + 8]       = e2;
            outs[(oc + 1) * 136 + px + 8] = e3;
        }
    }
    __syncthreads();
    #pragma unroll
    for (int j = 0; j < 8; ++j) {
        int idx = tid + 256 * j;
        int oc = idx >> 5, pxq = idx & 31;
        float4 v = *(const float4*)&outs[oc * 136 + pxq * 4];
        *(float4*)(g_act + ((size_t)b * CC + oc) * HWs + h * WW + pxq * 4) = v;
    }
}

// ---------------------------------------------------------------------------
// Kernel C: 3x3 conv 64->64 on act + bias + residual, tf32 tensor cores,
// software-pipelined: one sync/tap; row(dy+1) loaded during dx=0 region of dy;
// weights prefetched one tap ahead.
// ---------------------------------------------------------------------------
#define C_SMEM_FLOATS (2*64*136 + 2*64*68)
__global__ __launch_bounds__(256, 2) void conv2_kernel(const float* __restrict__ x,
                                                       const float* __restrict__ b_c,
                                                       float* __restrict__ out) {
    extern __shared__ float sm[];
    float* sval = sm;                    // [2][64 c][136 px]
    float* swk  = sm + 2 * 64 * 136;     // [2][64 oc][68]

    int tid = threadIdx.x;
    int b = blockIdx.x >> 7;
    int h = blockIdx.x & 127;

    int lane = tid & 31, wid = tid >> 5;
    int warp_m = wid & 3;
    int warp_n = wid >> 2;
    int lq = lane >> 2, lr = lane & 3;

    float4 acc[2][4];
    #pragma unroll
    for (int mt = 0; mt < 2; ++mt)
        #pragma unroll
        for (int nt = 0; nt < 4; ++nt) acc[mt][nt] = make_float4(0.f, 0.f, 0.f, 0.f);

    // row loader: stage act row y=h-1+dy into sval buffer `bufp`
    const float* actb = g_act + (size_t)b * CC * HWs;
    int ch = tid >> 7, j = tid & 127;

    // prologue: row dy=0 into buf0, weights tap0 into wbuf0
    {
        int y = h - 1;
        bool yok = (y >= 0);
        const float* arow = actb + (size_t)y * WW;
        int xg = j - 1;
        #pragma unroll
        for (int c0 = 0; c0 < 64; c0 += 2) {
            int c = c0 + ch;
            float v = (yok && xg >= 0) ? __ldg(arow + (size_t)c * HWs + xg) : 0.f;
            sval[c * 136 + j] = to_tf32(v);
        }
        if (tid < 128) {
            int c = tid >> 1, jj = 128 + (tid & 1);
            float v = (yok && jj < 129) ? __ldg(arow + (size_t)c * HWs + jj - 1) : 0.f;
            sval[c * 136 + jj] = to_tf32(v);
        }
        #pragma unroll
        for (int r = 0; r < 4; ++r) {
            int idx = tid + 256 * r;
            *(float4*)&swk[(idx >> 4) * 68 + (idx & 15) * 4] =
                *(const float4*)&g_wcT[idx * 4];
        }
    }
    __syncthreads();

    #pragma unroll 1
    for (int t = 0; t < KK; ++t) {
        int dy = t / 3, dx = t % 3;
        int wcur = t & 1, wnxt = wcur ^ 1;
        int abuf = dy & 1;
        bool pre = t < 8;

        float4 wreg[4];
        if (pre) {
            #pragma unroll
            for (int r = 0; r < 4; ++r)
                wreg[r] = *(const float4*)&g_wcT[(t + 1) * 4096 + (tid + 256 * r) * 4];
        }

        const float* sv = sval + abuf * 64 * 136;
        const float* wb = swk + wcur * 64 * 68;
        #pragma unroll
        for (int k0 = 0; k0 < 64; k0 += 8) {
            uint32_t afr[2][4];
            #pragma unroll
            for (int mt = 0; mt < 2; ++mt) {
                int pxb = warp_m * 32 + mt * 16 + lq + dx;
                afr[mt][0] = __float_as_uint(sv[(k0 + lr) * 136 + pxb]);
                afr[mt][1] = __float_as_uint(sv[(k0 + lr) * 136 + pxb + 8]);
                afr[mt][2] = __float_as_uint(sv[(k0 + lr + 4) * 136 + pxb]);
                afr[mt][3] = __float_as_uint(sv[(k0 + lr + 4) * 136 + pxb + 8]);
            }
            uint32_t bfr[4][2];
            #pragma unroll
            for (int nt = 0; nt < 4; ++nt) {
                int oc = warp_n * 32 + nt * 8 + lq;
                bfr[nt][0] = __float_as_uint(wb[oc * 68 + k0 + lr]);
                bfr[nt][1] = __float_as_uint(wb[oc * 68 + k0 + lr + 4]);
            }
            #pragma unroll
            for (int mt = 0; mt < 2; ++mt)
                #pragma unroll
                for (int nt = 0; nt < 4; ++nt)
                    mma8(acc[mt][nt], afr[mt], bfr[nt]);
        }

        // stage row dy+1 during the dx=0 region (read 3 syncs later)
        if (dx == 0 && dy < 2) {
            int y = h + dy;   // (h-1) + (dy+1)
            bool yok = (y < HH);
            const float* arow = actb + (size_t)y * WW;
            float* dstv = sval + (abuf ^ 1) * 64 * 136;
            int xg = j - 1;
            #pragma unroll
            for (int c0 = 0; c0 < 64; c0 += 2) {
                int c = c0 + ch;
                float v = (yok && xg >= 0) ? __ldg(arow + (size_t)c * HWs + xg) : 0.f;
                dstv[c * 136 + j] = to_tf32(v);
            }
            if (tid < 128) {
                int c = tid >> 1, jj = 128 + (tid & 1);
                float v = (yok && jj < 129) ? __ldg(arow + (size_t)c * HWs + jj - 1) : 0.f;
                dstv[c * 136 + jj] = to_tf32(v);
            }
        }
        if (pre) {
            #pragma unroll
            for (int r = 0; r < 4; ++r) {
                int idx = tid + 256 * r;
                *(float4*)&swk[wnxt * 64 * 68 + (idx >> 4) * 68 + (idx & 15) * 4] = wreg[r];
            }
        }
        __syncthreads();
    }

    // epilogue: bias, transpose via smem, residual + coalesced store
    float* outs = sm;
    #pragma unroll
    for (int mt = 0; mt < 2; ++mt) {
        #pragma unroll
        for (int nt = 0; nt < 4; ++nt) {
            int px = warp_m * 32 + mt * 16 + lq;
            int oc = warp_n * 32 + nt * 8 + 2 * lr;
            float b0 = __ldg(b_c + oc), b1 = __ldg(b_c + oc + 1);
            float4 v = acc[mt][nt];
            outs[oc * 136 + px]           = v.x + b0;
            outs[(oc + 1) * 136 + px]     = v.y + b1;
            outs[oc * 136 + px + 8]       = v.z + b0;
            outs[(oc + 1) * 136 + px + 8] = v.w + b1;
        }
    }
    __syncthreads();
    #pragma unroll
    for (int j2 = 0; j2 < 8; ++j2) {
        int idx = tid + 256 * j2;
        int oc = idx >> 5, pxq = idx & 31;
        size_t base = ((size_t)b * CC + oc) * HWs + h * WW + pxq * 4;
        float4 v = *(const float4*)&outs[oc * 136 + pxq * 4];
        float4 r = *(const float4*)(x + base);
        v.x += r.x; v.y += r.y; v.z += r.z; v.w += r.w;
        *(float4*)(out + base) = v;
    }
}

// ---------------------------------------------------------------------------
extern "C" void kernel_launch(void* const* d_in, const int* in_sizes, int n_in,
                              void* d_out, int out_size) {
    const float* x    = (const float*)d_in[0];
    const float* w_om = (const float*)d_in[1];
    const float* b_om = (const float*)d_in[2];
    const float* w_dc = (const float*)d_in[3];
    const float* b_dc = (const float*)d_in[4];
    const float* w_c  = (const float*)d_in[5];
    const float* b_c  = (const float*)d_in[6];
    float* out = (float*)d_out;

    cudaFuncSetAttribute(offmask_tc, cudaFuncAttributeMaxDynamicSharedMemorySize,
                         OM_SMEM_FLOATS * (int)sizeof(float));
    cudaFuncSetAttribute(deform_kernel, cudaFuncAttributeMaxDynamicSharedMemorySize,
                         B_SMEM_FLOATS * (int)sizeof(float));
    cudaFuncSetAttribute(conv2_kernel, cudaFuncAttributeMaxDynamicSharedMemorySize,
                         C_SMEM_FLOATS * (int)sizeof(float));

    wtrans_kernel<<<360, 256>>>(w_dc, w_c, w_om);
    transpose_kernel<<<BB * (HWs / 64), 256>>>(x);

    offmask_tc<<<BB * HH, 256, OM_SMEM_FLOATS * sizeof(float)>>>(x, b_om);

    deform_kernel<<<BB * HH, 256, B_SMEM_FLOATS * sizeof(float)>>>(b_dc);

    conv2_kernel<<<BB * HH, 256, C_SMEM_FLOATS * sizeof(float)>>>(x, b_c, out);
}